// round 10
// baseline (speedup 1.0000x reference)
#include <cuda_runtime.h>
#include <math.h>

#define HEADS 8
#define DIM 64
#define DH 64
#define DK 24
#define DHK 3
#define B 4
#define H 128
#define W 128
#define NTOK (H*W)           // 16384

typedef unsigned long long ull;

// ---------------- scratch ---------------------------------------------------
__device__ __align__(16) float g_kinp[B * DK * H * W];  // planar [b][ch][y][x]
__device__ __align__(16) float g_t1[B * DK * H * W];    // gelu(conv1) planar
__device__ __align__(16) float g_SW[2 * B * 24 * 64];   // S then W2
__device__ __align__(16) ull   g_wsp[2][1728];          // splatted (w,w) [tap*24+oc]

// ---------------- packed f32x2 helpers -------------------------------------
__device__ __forceinline__ ull pack2(float lo, float hi) {
    ull r; asm("mov.b64 %0, {%1,%2};" : "=l"(r) : "f"(lo), "f"(hi)); return r;
}
__device__ __forceinline__ void unpack2(ull v, float& lo, float& hi) {
    asm("mov.b64 {%0,%1}, %2;" : "=f"(lo), "=f"(hi) : "l"(v));
}
__device__ __forceinline__ void fma2(ull& d, ull a, ull b) {
    asm("fma.rn.f32x2 %0, %1, %2, %0;" : "+l"(d) : "l"(a), "l"(b));
}
__device__ __forceinline__ ull add2(ull a, ull b) {
    ull r; asm("add.rn.f32x2 %0, %1, %2;" : "=l"(r) : "l"(a), "l"(b)); return r;
}

__device__ __forceinline__ float gelu_exact(float x) {
    return 0.5f * x * (1.0f + erff(x * 0.70710678118654752f));
}

// ===========================================================================
// KWT: zero g_SW + build splatted transposed conv weights
// g_wsp[v][(i*9 + ky*3 + kx)*24 + oc] = (w, w)
// ===========================================================================
__global__ __launch_bounds__(256) void kwt_prep(
    const float* __restrict__ c1w, const float* __restrict__ c2w)
{
    const int tid = threadIdx.x;
    for (int i = tid; i < 12288; i += 256) g_SW[i] = 0.f;
    for (int i = tid; i < 1728; i += 256) {
        int oc = i / 72, r2 = i - oc * 72;
        float w1 = c1w[i], w2 = c2w[i];
        g_wsp[0][r2 * 24 + oc] = pack2(w1, w1);
        g_wsp[1][r2 * 24 + oc] = pack2(w2, w2);
    }
}

// ===========================================================================
// K1: k_inp = illu_map @ Wk (planar write) + S[b] += k_inp^T @ x
// grid (128 rows, B) block 256.  (unchanged from round 7 - proven 21.5us)
// ===========================================================================
__global__ __launch_bounds__(256, 4) void k1_kinp_S(
    const float* __restrict__ x, const float* __restrict__ im,
    const float* __restrict__ Wk)
{
    __shared__ __align__(16) float wk_s[576];
    __shared__ __align__(16) float k_s[128 * 25];
    __shared__ __align__(16) float buf[128 * 64];   // im_s then x_s

    const int tid = threadIdx.x;
    const int b = blockIdx.y;
    const int row = blockIdx.x;
    const int t0 = b * NTOK + row * 128;

    for (int i = tid; i < 576; i += 256) wk_s[i] = Wk[i];
    {
        const float* img = im + (size_t)t0 * 24;
        #pragma unroll
        for (int i = tid; i < 3072; i += 256) {
            int tok = i / 24, ci = i - tok * 24;
            buf[tok * 25 + ci] = img[i];
        }
    }
    __syncthreads();

    {
        const int tok = tid >> 1;
        const int j0 = (tid & 1) * 12;
        float acc[12];
        #pragma unroll
        for (int j = 0; j < 12; j++) acc[j] = 0.f;
        #pragma unroll 4
        for (int ci = 0; ci < 24; ci++) {
            float inv = buf[tok * 25 + ci];
            const float4* wp4 = (const float4*)&wk_s[ci * 24 + j0];
            float4 w0 = wp4[0], w1 = wp4[1], w2 = wp4[2];
            acc[0] += inv * w0.x; acc[1] += inv * w0.y; acc[2] += inv * w0.z; acc[3] += inv * w0.w;
            acc[4] += inv * w1.x; acc[5] += inv * w1.y; acc[6] += inv * w1.z; acc[7] += inv * w1.w;
            acc[8] += inv * w2.x; acc[9] += inv * w2.y; acc[10] += inv * w2.z; acc[11] += inv * w2.w;
        }
        #pragma unroll
        for (int j = 0; j < 12; j++) k_s[tok * 25 + j0 + j] = acc[j];
    }
    __syncthreads();

    {
        const float4* xg = (const float4*)(x + (size_t)t0 * 64);
        float4* xs4 = (float4*)buf;
        #pragma unroll
        for (int i = tid; i < 2048; i += 256) xs4[i] = xg[i];
    }
    {
        #pragma unroll
        for (int i = tid; i < 3072; i += 256) {
            int ch = i >> 7, xx = i & 127;
            g_kinp[(((size_t)b * 24 + ch) * H + row) * W + xx] = k_s[xx * 25 + ch];
        }
    }
    __syncthreads();

    {
        const int jj = tid >> 5;
        const int cc = tid & 31;
        ull s0 = 0, s1 = 0, s2 = 0;
        const ull* xp = (const ull*)buf;
        #pragma unroll 4
        for (int t = 0; t < 128; t++) {
            ull xv = xp[t * 32 + cc];
            float ka = k_s[t * 25 + jj * 3 + 0];
            float kb = k_s[t * 25 + jj * 3 + 1];
            float kc = k_s[t * 25 + jj * 3 + 2];
            fma2(s0, pack2(ka, ka), xv);
            fma2(s1, pack2(kb, kb), xv);
            fma2(s2, pack2(kc, kc), xv);
        }
        float lo, hi;
        float* Sg = g_SW + b * 1536;
        unpack2(s0, lo, hi);
        atomicAdd(&Sg[(jj * 3 + 0) * 64 + cc * 2], lo);
        atomicAdd(&Sg[(jj * 3 + 0) * 64 + cc * 2 + 1], hi);
        unpack2(s1, lo, hi);
        atomicAdd(&Sg[(jj * 3 + 1) * 64 + cc * 2], lo);
        atomicAdd(&Sg[(jj * 3 + 1) * 64 + cc * 2 + 1], hi);
        unpack2(s2, lo, hi);
        atomicAdd(&Sg[(jj * 3 + 2) * 64 + cc * 2], lo);
        atomicAdd(&Sg[(jj * 3 + 2) * 64 + cc * 2 + 1], hi);
    }
}

// ===========================================================================
// K2: per-head attention + W2. grid (8) block 256. (unchanged from round 7)
// ===========================================================================
__global__ __launch_bounds__(256) void k2_attn_W2(
    const float* __restrict__ Wq, const float* __restrict__ Wv,
    const float* __restrict__ Wp, const float* __restrict__ rescale)
{
    __shared__ __align__(16) float wqv_s[64 * 65];
    __shared__ float s_S[4 * 3 * 64];
    __shared__ float s_A[4 * 3 * 64];
    __shared__ float s_M[4 * 64 * 3];
    __shared__ float wp_s[3 * 24];

    const int h = blockIdx.x;
    const int tid = threadIdx.x;

    for (int i = tid; i < 4096; i += 256) {
        int c = i >> 6, d = i & 63;
        wqv_s[c * 65 + d] = Wq[c * 512 + h * 64 + d];
    }
    for (int i = tid; i < 768; i += 256) {
        int b = i / 192, rem = i - b * 192;
        s_S[i] = g_SW[b * 1536 + h * 3 * 64 + rem];
    }
    if (tid < 72) {
        int k = tid / 24, o = tid - k * 24;
        wp_s[tid] = Wp[(k * 8 + h) * 24 + o];
    }
    __syncthreads();

    const int b = tid >> 6;
    const int d = tid & 63;
    const float sc = rescale[h] * 0.125f;

    {
        float a0 = 0.f, a1 = 0.f, a2 = 0.f;
        const float* Sb = s_S + b * 192;
        #pragma unroll 8
        for (int c = 0; c < 64; c++) {
            float wq = wqv_s[c * 65 + d];
            a0 += Sb[c] * wq;
            a1 += Sb[64 + c] * wq;
            a2 += Sb[128 + c] * wq;
        }
        s_A[(b * 3 + 0) * 64 + d] = a0 * sc;
        s_A[(b * 3 + 1) * 64 + d] = a1 * sc;
        s_A[(b * 3 + 2) * 64 + d] = a2 * sc;
    }
    __syncthreads();

    {
        const int wid = tid >> 5, lane = tid & 31;
        for (int rowi = wid; rowi < 12; rowi += 8) {
            float v0 = s_A[rowi * 64 + lane];
            float v1 = s_A[rowi * 64 + 32 + lane];
            float m = fmaxf(v0, v1);
            #pragma unroll
            for (int off = 16; off; off >>= 1) m = fmaxf(m, __shfl_xor_sync(~0u, m, off));
            float e0 = __expf(v0 - m), e1 = __expf(v1 - m);
            float s = e0 + e1;
            #pragma unroll
            for (int off = 16; off; off >>= 1) s += __shfl_xor_sync(~0u, s, off);
            float inv = 1.0f / s;
            s_A[rowi * 64 + lane] = e0 * inv;
            s_A[rowi * 64 + 32 + lane] = e1 * inv;
        }
    }
    __syncthreads();

    for (int i = tid; i < 4096; i += 256) {
        int c = i >> 6, dd = i & 63;
        wqv_s[c * 65 + dd] = Wv[c * 512 + h * 64 + dd];
    }
    __syncthreads();

    {
        const int c = tid & 63;
        float m0 = 0.f, m1 = 0.f, m2 = 0.f;
        const float* Ab = s_A + b * 192;
        const float* wvr = wqv_s + c * 65;
        #pragma unroll 8
        for (int dd = 0; dd < 64; dd++) {
            float wv = wvr[dd];
            m0 += wv * Ab[dd];
            m1 += wv * Ab[64 + dd];
            m2 += wv * Ab[128 + dd];
        }
        s_M[(b * 64 + c) * 3 + 0] = m0;
        s_M[(b * 64 + c) * 3 + 1] = m1;
        s_M[(b * 64 + c) * 3 + 2] = m2;
    }
    __syncthreads();

    {
        const int c = tid & 63;
        const float* mrow = &s_M[(b * 64 + c) * 3];
        float m0 = mrow[0], m1 = mrow[1], m2 = mrow[2];
        float* W2g = g_SW + 6144 + b * 1536 + c * 24;
        #pragma unroll
        for (int o = 0; o < 24; o++) {
            float v = m0 * wp_s[o] + m1 * wp_s[24 + o] + m2 * wp_s[48 + o];
            atomicAdd(&W2g[o], v);
        }
    }
}

// ===========================================================================
// conv helper: 16 px x 1 oc, px-pair f32x2 accs, input from [r][24][132] smem
// ===========================================================================
__device__ __forceinline__ void conv_row16(
    const float* kin, const ull* wsp, int oc, int xseg, ull* acc)
{
    const int g = oc >> 3;
    const float* kb = kin + g * (8 * 132) + xseg * 16;
    const ull* wb = wsp + oc;
    #pragma unroll
    for (int i = 0; i < 8; i++) {
        #pragma unroll
        for (int ky = 0; ky < 3; ky++) {
            const float4* rp = (const float4*)(kb + ky * 3168 + i * 132);
            float4 f0 = rp[0], f1 = rp[1], f2 = rp[2], f3 = rp[3], f4 = rp[4];
            float in[20] = {f0.x, f0.y, f0.z, f0.w, f1.x, f1.y, f1.z, f1.w,
                            f2.x, f2.y, f2.z, f2.w, f3.x, f3.y, f3.z, f3.w,
                            f4.x, f4.y, f4.z, f4.w};
            const int tb = (i * 9 + ky * 3) * 24;
            ull w0 = wb[tb], w1 = wb[tb + 24], w2 = wb[tb + 48];
            #pragma unroll
            for (int q = 0; q < 8; q++) {
                fma2(acc[q], w0, pack2(in[2 * q], in[2 * q + 1]));
                fma2(acc[q], w1, pack2(in[2 * q + 1], in[2 * q + 2]));
                fma2(acc[q], w2, pack2(in[2 * q + 2], in[2 * q + 3]));
            }
        }
    }
}

// stage 3 planar rows (gy = y-1..y+1) of src into kin [3][24][132], px_s=gx+1
template<int NT>
__device__ __forceinline__ void stage_rows(
    float* kin, const float* src_base, int b, int y, int tid)
{
    #pragma unroll
    for (int r = 0; r < 3; r++) {
        int gy = y - 1 + r;
        if ((unsigned)gy < (unsigned)H) {
            const float* src = src_base + ((size_t)(b * 24) * H + gy) * W;
            for (int inner = tid; inner < 3072; inner += NT) {
                int ch = inner >> 7, gx = inner & 127;
                kin[r * 3168 + ch * 132 + gx + 1] = src[ch * NTOK + gx];
            }
        } else {
            for (int inner = tid; inner < 3072; inner += NT) {
                int ch = inner >> 7, gx = inner & 127;
                kin[r * 3168 + ch * 132 + gx + 1] = 0.f;
            }
        }
    }
    for (int t = tid; t < 288; t += NT) {
        int rl = t >> 2, c = t & 3;
        kin[rl * 132 + (c == 0 ? 0 : 128 + c)] = 0.f;
    }
}

// ===========================================================================
// K4A: conv1 + GELU -> g_t1.  grid (128, B), block 192 = oc(24) x xseg(8).
// smem: kin [3][24][132] + splatted w1 (1728 ull) = 51.8 KB -> 4 blocks/SM.
// ===========================================================================
#define K4A_SMEM ((9504 + 3456) * 4)

__global__ __launch_bounds__(192) void k4a_conv1()
{
    extern __shared__ __align__(16) float s[];
    float* kin = s;
    ull* wsp = (ull*)(s + 9504);

    const int tid = threadIdx.x;
    const int b = blockIdx.y;
    const int y = blockIdx.x;

    {
        const float4* src = (const float4*)&g_wsp[0][0];
        float4* dst = (float4*)wsp;
        for (int i = tid; i < 864; i += 192) dst[i] = src[i];
    }
    stage_rows<192>(kin, g_kinp, b, y, tid);
    __syncthreads();

    const int oc = tid >> 3, xseg = tid & 7;
    ull acc[8];
    #pragma unroll
    for (int q = 0; q < 8; q++) acc[q] = 0ull;
    conv_row16(kin, wsp, oc, xseg, acc);

    float v[16];
    #pragma unroll
    for (int q = 0; q < 8; q++) unpack2(acc[q], v[2 * q], v[2 * q + 1]);
    #pragma unroll
    for (int q = 0; q < 16; q++) v[q] = gelu_exact(v[q]);
    float4* dst = (float4*)(g_t1 + (((size_t)b * 24 + oc) * H + y) * W + xseg * 16);
    dst[0] = make_float4(v[0], v[1], v[2], v[3]);
    dst[1] = make_float4(v[4], v[5], v[6], v[7]);
    dst[2] = make_float4(v[8], v[9], v[10], v[11]);
    dst[3] = make_float4(v[12], v[13], v[14], v[15]);
}

// ===========================================================================
// K4B: conv2 (from g_t1) + projection fea@W2+bp + store.
// grid (128, B), block 256. smem: t1s[9504] + w2sp[3456] + W2s[1536] + bps[32]
// = 58.1 KB -> 3 blocks/SM.  c2s [24][130] aliases t1s after conv sync.
// ===========================================================================
#define K4B_SMEM ((9504 + 3456 + 1536 + 32) * 4)

__global__ __launch_bounds__(256) void k4b_conv2_proj(
    const float* __restrict__ fea, const float* __restrict__ bp,
    float* __restrict__ out)
{
    extern __shared__ __align__(16) float s[];
    float* t1s = s;
    ull* wsp = (ull*)(s + 9504);
    float* W2s = s + 9504 + 3456;
    float* bps = W2s + 1536;

    const int tid = threadIdx.x;
    const int b = blockIdx.y;
    const int y = blockIdx.x;

    {
        const float4* src = (const float4*)&g_wsp[1][0];
        float4* dst = (float4*)wsp;
        for (int i = tid; i < 864; i += 256) dst[i] = src[i];
    }
    {
        const float* w2g = g_SW + 6144 + b * 1536;
        for (int i = tid; i < 1536; i += 256) W2s[i] = w2g[i];
    }
    if (tid < 24) bps[tid] = bp[tid];
    stage_rows<256>(t1s, g_t1, b, y, tid);
    __syncthreads();

    // conv2 on first 192 threads; accs stay in regs across the sync
    ull cacc[8];
    #pragma unroll
    for (int q = 0; q < 8; q++) cacc[q] = 0ull;
    const int oc = tid >> 3, xseg = tid & 7;
    if (tid < 192)
        conv_row16(t1s, wsp, oc, xseg, cacc);
    __syncthreads();   // all conv reads of t1s done

    // write conv2 results into c2s (aliases head of t1s)
    float* c2s = t1s;  // [24][130]
    if (tid < 192) {
        float cv[16];
        #pragma unroll
        for (int q = 0; q < 8; q++) unpack2(cacc[q], cv[2 * q], cv[2 * q + 1]);
        float* dst = c2s + oc * 130 + xseg * 16;
        #pragma unroll
        for (int q = 0; q < 8; q++)
            *(ull*)(dst + 2 * q) = pack2(cv[2 * q], cv[2 * q + 1]);
    }
    __syncthreads();

    // projection: lane pair (2p,2p+1) shares pixel p; each does 32 of 64 c's
    {
        const int px = tid >> 1;
        const int half = tid & 1;
        ull acc[12];
        #pragma unroll
        for (int m = 0; m < 12; m++) acc[m] = 0ull;
        const float4* fea4 = (const float4*)(fea +
            ((size_t)b * NTOK + (size_t)y * W + px) * 64) + half * 8;
        #pragma unroll
        for (int c4 = 0; c4 < 8; c4++) {
            float4 f = fea4[c4];
            float fe[4] = {f.x, f.y, f.z, f.w};
            #pragma unroll
            for (int e = 0; e < 4; e++) {
                ull f2 = pack2(fe[e], fe[e]);
                const ulonglong2* wrow =
                    (const ulonglong2*)(W2s + ((half * 8 + c4) * 4 + e) * 24);
                #pragma unroll
                for (int m = 0; m < 6; m++) {
                    ulonglong2 wp = wrow[m];
                    fma2(acc[2 * m], wp.x, f2);
                    fma2(acc[2 * m + 1], wp.y, f2);
                }
            }
        }
        #pragma unroll
        for (int m = 0; m < 12; m++) {
            ull other = __shfl_xor_sync(~0u, acc[m], 1);
            acc[m] = add2(acc[m], other);
        }
        if (half == 0) {
            float res[24];
            #pragma unroll
            for (int m = 0; m < 12; m++) {
                float lo, hi; unpack2(acc[m], lo, hi);
                res[2 * m] = lo + bps[2 * m];
                res[2 * m + 1] = hi + bps[2 * m + 1];
            }
            #pragma unroll
            for (int ch = 0; ch < 24; ch++)
                res[ch] += c2s[ch * 130 + px];
            float4* og = (float4*)(out +
                ((size_t)b * NTOK + (size_t)y * W + px) * 24);
            #pragma unroll
            for (int q = 0; q < 6; q++)
                og[q] = make_float4(res[q * 4], res[q * 4 + 1],
                                    res[q * 4 + 2], res[q * 4 + 3]);
        }
    }
}

// ===========================================================================
extern "C" void kernel_launch(void* const* d_in, const int* in_sizes, int n_in,
                              void* d_out, int out_size)
{
    const float* x = (const float*)d_in[0];
    const float* fea = (const float*)d_in[1];
    const float* im = (const float*)d_in[2];
    const float* Wq = (const float*)d_in[3];
    const float* Wk = (const float*)d_in[4];
    const float* Wv = (const float*)d_in[5];
    const float* rescale = (const float*)d_in[6];
    const float* Wp = (const float*)d_in[7];
    const float* bp = (const float*)d_in[8];
    const float* c1w = (const float*)d_in[9];
    const float* c2w = (const float*)d_in[10];
    float* out = (float*)d_out;

    cudaFuncSetAttribute(k4a_conv1,
                         cudaFuncAttributeMaxDynamicSharedMemorySize, K4A_SMEM);
    cudaFuncSetAttribute(k4b_conv2_proj,
                         cudaFuncAttributeMaxDynamicSharedMemorySize, K4B_SMEM);

    kwt_prep<<<1, 256>>>(c1w, c2w);
    k1_kinp_S<<<dim3(128, B), 256>>>(x, im, Wk);
    k2_attn_W2<<<dim3(HEADS), 256>>>(Wq, Wv, Wp, rescale);
    k4a_conv1<<<dim3(128, B), 192, K4A_SMEM>>>();
    k4b_conv2_proj<<<dim3(128, B), 256, K4B_SMEM>>>(fea, bp, out);
}

// round 11
// speedup vs baseline: 1.2608x; 1.2608x over previous
#include <cuda_runtime.h>
#include <math.h>

#define HEADS 8
#define DIM 64
#define DH 64
#define DK 24
#define DHK 3
#define B 4
#define H 128
#define W 128
#define NTOK (H*W)           // 16384

typedef unsigned long long ull;

// ---------------- scratch ---------------------------------------------------
__device__ __align__(16) float g_kinp[B * DK * H * W];  // planar [b][ch][y][x]
__device__ __align__(16) float g_t1[B * DK * H * W];    // gelu(conv1) planar
__device__ __align__(16) float g_SW[2 * B * 24 * 64];   // S then W2
__device__ __align__(16) ull   g_wsp[2][1728];          // splatted (w,w) [tap*24+oc]

// ---------------- packed f32x2 helpers -------------------------------------
__device__ __forceinline__ ull pack2(float lo, float hi) {
    ull r; asm("mov.b64 %0, {%1,%2};" : "=l"(r) : "f"(lo), "f"(hi)); return r;
}
__device__ __forceinline__ void unpack2(ull v, float& lo, float& hi) {
    asm("mov.b64 {%0,%1}, %2;" : "=f"(lo), "=f"(hi) : "l"(v));
}
__device__ __forceinline__ void fma2(ull& d, ull a, ull b) {
    asm("fma.rn.f32x2 %0, %1, %2, %0;" : "+l"(d) : "l"(a), "l"(b));
}
__device__ __forceinline__ ull add2(ull a, ull b) {
    ull r; asm("add.rn.f32x2 %0, %1, %2;" : "=l"(r) : "l"(a), "l"(b)); return r;
}

__device__ __forceinline__ float gelu_exact(float x) {
    return 0.5f * x * (1.0f + erff(x * 0.70710678118654752f));
}

// ===========================================================================
// KWT: zero g_SW + build splatted transposed conv weights
// ===========================================================================
__global__ __launch_bounds__(256) void kwt_prep(
    const float* __restrict__ c1w, const float* __restrict__ c2w)
{
    const int tid = threadIdx.x;
    for (int i = tid; i < 12288; i += 256) g_SW[i] = 0.f;
    for (int i = tid; i < 1728; i += 256) {
        int oc = i / 72, r2 = i - oc * 72;
        float w1 = c1w[i], w2 = c2w[i];
        g_wsp[0][r2 * 24 + oc] = pack2(w1, w1);
        g_wsp[1][r2 * 24 + oc] = pack2(w2, w2);
    }
}

// ===========================================================================
// K1: k_inp = illu_map @ Wk (planar write) + S[b] += k_inp^T @ x
// (byte-identical to round 7 - measured 21.5us)
// ===========================================================================
__global__ __launch_bounds__(256, 4) void k1_kinp_S(
    const float* __restrict__ x, const float* __restrict__ im,
    const float* __restrict__ Wk)
{
    __shared__ __align__(16) float wk_s[576];
    __shared__ __align__(16) float k_s[128 * 25];
    __shared__ __align__(16) float buf[128 * 64];   // im_s then x_s

    const int tid = threadIdx.x;
    const int b = blockIdx.y;
    const int row = blockIdx.x;
    const int t0 = b * NTOK + row * 128;

    for (int i = tid; i < 576; i += 256) wk_s[i] = Wk[i];
    {
        const float* img = im + (size_t)t0 * 24;
        #pragma unroll
        for (int i = tid; i < 3072; i += 256) {
            int tok = i / 24, ci = i - tok * 24;
            buf[tok * 25 + ci] = img[i];
        }
    }
    __syncthreads();

    {
        const int tok = tid >> 1;
        const int j0 = (tid & 1) * 12;
        float acc[12];
        #pragma unroll
        for (int j = 0; j < 12; j++) acc[j] = 0.f;
        #pragma unroll 4
        for (int ci = 0; ci < 24; ci++) {
            float inv = buf[tok * 25 + ci];
            const float4* wp4 = (const float4*)&wk_s[ci * 24 + j0];
            float4 w0 = wp4[0], w1 = wp4[1], w2 = wp4[2];
            acc[0] += inv * w0.x; acc[1] += inv * w0.y; acc[2] += inv * w0.z; acc[3] += inv * w0.w;
            acc[4] += inv * w1.x; acc[5] += inv * w1.y; acc[6] += inv * w1.z; acc[7] += inv * w1.w;
            acc[8] += inv * w2.x; acc[9] += inv * w2.y; acc[10] += inv * w2.z; acc[11] += inv * w2.w;
        }
        #pragma unroll
        for (int j = 0; j < 12; j++) k_s[tok * 25 + j0 + j] = acc[j];
    }
    __syncthreads();

    {
        const float4* xg = (const float4*)(x + (size_t)t0 * 64);
        float4* xs4 = (float4*)buf;
        #pragma unroll
        for (int i = tid; i < 2048; i += 256) xs4[i] = xg[i];
    }
    {
        #pragma unroll
        for (int i = tid; i < 3072; i += 256) {
            int ch = i >> 7, xx = i & 127;
            g_kinp[(((size_t)b * 24 + ch) * H + row) * W + xx] = k_s[xx * 25 + ch];
        }
    }
    __syncthreads();

    {
        const int jj = tid >> 5;
        const int cc = tid & 31;
        ull s0 = 0, s1 = 0, s2 = 0;
        const ull* xp = (const ull*)buf;
        #pragma unroll 4
        for (int t = 0; t < 128; t++) {
            ull xv = xp[t * 32 + cc];
            float ka = k_s[t * 25 + jj * 3 + 0];
            float kb = k_s[t * 25 + jj * 3 + 1];
            float kc = k_s[t * 25 + jj * 3 + 2];
            fma2(s0, pack2(ka, ka), xv);
            fma2(s1, pack2(kb, kb), xv);
            fma2(s2, pack2(kc, kc), xv);
        }
        float lo, hi;
        float* Sg = g_SW + b * 1536;
        unpack2(s0, lo, hi);
        atomicAdd(&Sg[(jj * 3 + 0) * 64 + cc * 2], lo);
        atomicAdd(&Sg[(jj * 3 + 0) * 64 + cc * 2 + 1], hi);
        unpack2(s1, lo, hi);
        atomicAdd(&Sg[(jj * 3 + 1) * 64 + cc * 2], lo);
        atomicAdd(&Sg[(jj * 3 + 1) * 64 + cc * 2 + 1], hi);
        unpack2(s2, lo, hi);
        atomicAdd(&Sg[(jj * 3 + 2) * 64 + cc * 2], lo);
        atomicAdd(&Sg[(jj * 3 + 2) * 64 + cc * 2 + 1], hi);
    }
}

// ===========================================================================
// K2: per-head attention + W2. grid (8) block 256. (round 7, proven)
// ===========================================================================
__global__ __launch_bounds__(256) void k2_attn_W2(
    const float* __restrict__ Wq, const float* __restrict__ Wv,
    const float* __restrict__ Wp, const float* __restrict__ rescale)
{
    __shared__ __align__(16) float wqv_s[64 * 65];
    __shared__ float s_S[4 * 3 * 64];
    __shared__ float s_A[4 * 3 * 64];
    __shared__ float s_M[4 * 64 * 3];
    __shared__ float wp_s[3 * 24];

    const int h = blockIdx.x;
    const int tid = threadIdx.x;

    for (int i = tid; i < 4096; i += 256) {
        int c = i >> 6, d = i & 63;
        wqv_s[c * 65 + d] = Wq[c * 512 + h * 64 + d];
    }
    for (int i = tid; i < 768; i += 256) {
        int b = i / 192, rem = i - b * 192;
        s_S[i] = g_SW[b * 1536 + h * 3 * 64 + rem];
    }
    if (tid < 72) {
        int k = tid / 24, o = tid - k * 24;
        wp_s[tid] = Wp[(k * 8 + h) * 24 + o];
    }
    __syncthreads();

    const int b = tid >> 6;
    const int d = tid & 63;
    const float sc = rescale[h] * 0.125f;

    {
        float a0 = 0.f, a1 = 0.f, a2 = 0.f;
        const float* Sb = s_S + b * 192;
        #pragma unroll 8
        for (int c = 0; c < 64; c++) {
            float wq = wqv_s[c * 65 + d];
            a0 += Sb[c] * wq;
            a1 += Sb[64 + c] * wq;
            a2 += Sb[128 + c] * wq;
        }
        s_A[(b * 3 + 0) * 64 + d] = a0 * sc;
        s_A[(b * 3 + 1) * 64 + d] = a1 * sc;
        s_A[(b * 3 + 2) * 64 + d] = a2 * sc;
    }
    __syncthreads();

    {
        const int wid = tid >> 5, lane = tid & 31;
        for (int rowi = wid; rowi < 12; rowi += 8) {
            float v0 = s_A[rowi * 64 + lane];
            float v1 = s_A[rowi * 64 + 32 + lane];
            float m = fmaxf(v0, v1);
            #pragma unroll
            for (int off = 16; off; off >>= 1) m = fmaxf(m, __shfl_xor_sync(~0u, m, off));
            float e0 = __expf(v0 - m), e1 = __expf(v1 - m);
            float s2 = e0 + e1;
            #pragma unroll
            for (int off = 16; off; off >>= 1) s2 += __shfl_xor_sync(~0u, s2, off);
            float inv = 1.0f / s2;
            s_A[rowi * 64 + lane] = e0 * inv;
            s_A[rowi * 64 + 32 + lane] = e1 * inv;
        }
    }
    __syncthreads();

    for (int i = tid; i < 4096; i += 256) {
        int c = i >> 6, dd = i & 63;
        wqv_s[c * 65 + dd] = Wv[c * 512 + h * 64 + dd];
    }
    __syncthreads();

    {
        const int c = tid & 63;
        float m0 = 0.f, m1 = 0.f, m2 = 0.f;
        const float* Ab = s_A + b * 192;
        const float* wvr = wqv_s + c * 65;
        #pragma unroll 8
        for (int dd = 0; dd < 64; dd++) {
            float wv = wvr[dd];
            m0 += wv * Ab[dd];
            m1 += wv * Ab[64 + dd];
            m2 += wv * Ab[128 + dd];
        }
        s_M[(b * 64 + c) * 3 + 0] = m0;
        s_M[(b * 64 + c) * 3 + 1] = m1;
        s_M[(b * 64 + c) * 3 + 2] = m2;
    }
    __syncthreads();

    {
        const int c = tid & 63;
        const float* mrow = &s_M[(b * 64 + c) * 3];
        float m0 = mrow[0], m1 = mrow[1], m2 = mrow[2];
        float* W2g = g_SW + 6144 + b * 1536 + c * 24;
        #pragma unroll
        for (int o = 0; o < 24; o++) {
            float v = m0 * wp_s[o] + m1 * wp_s[24 + o] + m2 * wp_s[48 + o];
            atomicAdd(&W2g[o], v);
        }
    }
}

// ===========================================================================
// Conflict-free conv: thread = (ocp: oc-pair 2ocp,2ocp+1 in one group,
// xseg: 4 consecutive px). Input smem layout [r][ch][136] (4-float pads both
// ends). Lanes = consecutive xseg -> 16B-stride float4 loads, conflict-free.
// Warp = single ocp -> weight LDS.128 broadcast.
// ===========================================================================
__device__ __forceinline__ void conv_row4(
    const float* kin, const ull* wsp, int ocp, int xseg, ull acc[4])
{
    const int g = ocp >> 2;                    // oc0 = 2*ocp; g = oc0>>3
    const float* kb = kin + (g * 8) * 136 + xseg * 4;
    const int oc0 = ocp * 2;
    #pragma unroll
    for (int i = 0; i < 8; i++) {
        #pragma unroll
        for (int r = 0; r < 3; r++) {
            const float* rp = kb + r * 3264 + i * 136;
            float4 A = *(const float4*)(rp);        // in[-4..-1]
            float4 Bv = *(const float4*)(rp + 4);   // in[0..3]
            float4 C = *(const float4*)(rp + 8);    // in[4..7]
            ull P0 = pack2(A.w, Bv.x);    // (in-1, in0)
            ull P1 = pack2(Bv.x, Bv.y);   // (in0, in1)
            ull P2 = pack2(Bv.y, Bv.z);   // (in1, in2)
            ull P3 = pack2(Bv.z, Bv.w);   // (in2, in3)
            ull P4 = pack2(Bv.w, C.x);    // (in3, in4)
            const int tb = (i * 9 + r * 3) * 24 + oc0;
            {
                ulonglong2 wv = *(const ulonglong2*)&wsp[tb];          // kx=0
                fma2(acc[0], wv.x, P0); fma2(acc[1], wv.x, P2);
                fma2(acc[2], wv.y, P0); fma2(acc[3], wv.y, P2);
            }
            {
                ulonglong2 wv = *(const ulonglong2*)&wsp[tb + 24];     // kx=1
                fma2(acc[0], wv.x, P1); fma2(acc[1], wv.x, P3);
                fma2(acc[2], wv.y, P1); fma2(acc[3], wv.y, P3);
            }
            {
                ulonglong2 wv = *(const ulonglong2*)&wsp[tb + 48];     // kx=2
                fma2(acc[0], wv.x, P2); fma2(acc[1], wv.x, P4);
                fma2(acc[2], wv.y, P2); fma2(acc[3], wv.y, P4);
            }
        }
    }
}

// stage 3 planar rows (gy = y-1..y+1) into kin [3][24][136] (pads zeroed)
template<int NT>
__device__ __forceinline__ void stage3(
    float* kin, const float* src_base, int b, int y, int tid)
{
    #pragma unroll
    for (int r = 0; r < 3; r++) {
        int gy = y - 1 + r;
        if ((unsigned)gy < (unsigned)H) {
            const float* sp = src_base + ((size_t)(b * 24) * H + gy) * W;
            for (int i = tid; i < 3072; i += NT) {
                int ch = i >> 7, gx = i & 127;
                kin[r * 3264 + ch * 136 + 4 + gx] = sp[ch * NTOK + gx];
            }
        } else {
            for (int i = tid; i < 3072; i += NT) {
                int ch = i >> 7, gx = i & 127;
                kin[r * 3264 + ch * 136 + 4 + gx] = 0.f;
            }
        }
    }
    for (int t = tid; t < 576; t += NT) {
        int rc = t >> 3, c = t & 7;
        int r = rc / 24, ch = rc - r * 24;
        kin[r * 3264 + ch * 136 + (c < 4 ? c : 128 + c)] = 0.f;
    }
}

// ===========================================================================
// K4A: conv1 + GELU -> g_t1.  grid (128, B), block 384 = ocp(12) x xseg(32).
// smem: kin [3][24][136] (39.2KB) + wsp ull[1728] (13.8KB) = 53KB.
// ===========================================================================
#define K4A_SMEM ((9792 + 3456) * 4)

__global__ __launch_bounds__(384, 3) void k4a_conv1()
{
    extern __shared__ __align__(16) float s[];
    float* kin = s;
    ull* wsp = (ull*)(s + 9792);

    const int tid = threadIdx.x;
    const int b = blockIdx.y;
    const int y = blockIdx.x;

    {
        const float4* src = (const float4*)&g_wsp[0][0];
        float4* dst = (float4*)wsp;
        for (int i = tid; i < 864; i += 384) dst[i] = src[i];
    }
    stage3<384>(kin, g_kinp, b, y, tid);
    __syncthreads();

    const int ocp = tid >> 5, xseg = tid & 31;
    ull acc[4] = {0ull, 0ull, 0ull, 0ull};
    conv_row4(kin, wsp, ocp, xseg, acc);

    float v[8];
    unpack2(acc[0], v[0], v[1]); unpack2(acc[1], v[2], v[3]);   // oc0 px0..3
    unpack2(acc[2], v[4], v[5]); unpack2(acc[3], v[6], v[7]);   // oc1 px0..3
    #pragma unroll
    for (int q = 0; q < 8; q++) v[q] = gelu_exact(v[q]);
    const int oc0 = ocp * 2;
    float4* d0 = (float4*)(g_t1 + (((size_t)b * 24 + oc0) * H + y) * W + xseg * 4);
    float4* d1 = (float4*)(g_t1 + (((size_t)b * 24 + oc0 + 1) * H + y) * W + xseg * 4);
    *d0 = make_float4(v[0], v[1], v[2], v[3]);
    *d1 = make_float4(v[4], v[5], v[6], v[7]);
}

// ===========================================================================
// K4B: conv2 (from g_t1) + projection fea@W2+bp + store.
// grid (128, B), block 384. smem: t1s[9792] + wsp[3456] = 53KB.
// After conv: c2s [24][132] aliases t1s head; W2s+bps alias wsp region.
// ===========================================================================
#define K4B_SMEM ((9792 + 3456) * 4)

__global__ __launch_bounds__(384, 3) void k4b_conv2_proj(
    const float* __restrict__ fea, const float* __restrict__ bp,
    float* __restrict__ out)
{
    extern __shared__ __align__(16) float s[];
    float* t1s = s;
    ull* wsp = (ull*)(s + 9792);

    const int tid = threadIdx.x;
    const int b = blockIdx.y;
    const int y = blockIdx.x;

    {
        const float4* src = (const float4*)&g_wsp[1][0];
        float4* dst = (float4*)wsp;
        for (int i = tid; i < 864; i += 384) dst[i] = src[i];
    }
    stage3<384>(t1s, g_t1, b, y, tid);
    __syncthreads();

    const int ocp = tid >> 5, xseg = tid & 31;
    ull cacc[4] = {0ull, 0ull, 0ull, 0ull};
    conv_row4(t1s, wsp, ocp, xseg, cacc);
    __syncthreads();   // all conv reads of t1s/wsp done

    // write conv2 into c2s (aliases t1s head); load W2+bp into wsp region
    float* c2s = t1s;                  // [24][132]
    float* W2s = (float*)wsp;          // 1536 floats
    float* bps = W2s + 1536;
    {
        const int oc0 = ocp * 2;
        float cv[8];
        unpack2(cacc[0], cv[0], cv[1]); unpack2(cacc[1], cv[2], cv[3]);
        unpack2(cacc[2], cv[4], cv[5]); unpack2(cacc[3], cv[6], cv[7]);
        *(float4*)(c2s + oc0 * 132 + xseg * 4) = make_float4(cv[0], cv[1], cv[2], cv[3]);
        *(float4*)(c2s + (oc0 + 1) * 132 + xseg * 4) = make_float4(cv[4], cv[5], cv[6], cv[7]);
    }
    {
        const float* w2g = g_SW + 6144 + b * 1536;
        for (int i = tid; i < 1536; i += 384) W2s[i] = w2g[i];
        if (tid < 24) bps[tid] = bp[tid];
    }
    __syncthreads();

    // projection on threads 0..255: lane pair (2p,2p+1) shares pixel p
    if (tid < 256) {
        const int px = tid >> 1;
        const int half = tid & 1;
        ull acc[12];
        #pragma unroll
        for (int m = 0; m < 12; m++) acc[m] = 0ull;
        const float4* fea4 = (const float4*)(fea +
            ((size_t)b * NTOK + (size_t)y * W + px) * 64) + half * 8;
        #pragma unroll
        for (int c4 = 0; c4 < 8; c4++) {
            float4 f = fea4[c4];
            float fe[4] = {f.x, f.y, f.z, f.w};
            #pragma unroll
            for (int e = 0; e < 4; e++) {
                ull f2 = pack2(fe[e], fe[e]);
                const ulonglong2* wrow =
                    (const ulonglong2*)(W2s + ((half * 8 + c4) * 4 + e) * 24);
                #pragma unroll
                for (int m = 0; m < 6; m++) {
                    ulonglong2 wp = wrow[m];
                    fma2(acc[2 * m], wp.x, f2);
                    fma2(acc[2 * m + 1], wp.y, f2);
                }
            }
        }
        #pragma unroll
        for (int m = 0; m < 12; m++) {
            ull other = __shfl_xor_sync(~0u, acc[m], 1);
            acc[m] = add2(acc[m], other);
        }
        if (half == 0) {
            float res[24];
            #pragma unroll
            for (int m = 0; m < 12; m++) {
                float lo, hi; unpack2(acc[m], lo, hi);
                res[2 * m] = lo + bps[2 * m];
                res[2 * m + 1] = hi + bps[2 * m + 1];
            }
            #pragma unroll
            for (int ch = 0; ch < 24; ch++)
                res[ch] += c2s[ch * 132 + px];
            float4* og = (float4*)(out +
                ((size_t)b * NTOK + (size_t)y * W + px) * 24);
            #pragma unroll
            for (int q = 0; q < 6; q++)
                og[q] = make_float4(res[q * 4], res[q * 4 + 1],
                                    res[q * 4 + 2], res[q * 4 + 3]);
        }
    }
}

// ===========================================================================
extern "C" void kernel_launch(void* const* d_in, const int* in_sizes, int n_in,
                              void* d_out, int out_size)
{
    const float* x = (const float*)d_in[0];
    const float* fea = (const float*)d_in[1];
    const float* im = (const float*)d_in[2];
    const float* Wq = (const float*)d_in[3];
    const float* Wk = (const float*)d_in[4];
    const float* Wv = (const float*)d_in[5];
    const float* rescale = (const float*)d_in[6];
    const float* Wp = (const float*)d_in[7];
    const float* bp = (const float*)d_in[8];
    const float* c1w = (const float*)d_in[9];
    const float* c2w = (const float*)d_in[10];
    float* out = (float*)d_out;

    cudaFuncSetAttribute(k4a_conv1,
                         cudaFuncAttributeMaxDynamicSharedMemorySize, K4A_SMEM);
    cudaFuncSetAttribute(k4b_conv2_proj,
                         cudaFuncAttributeMaxDynamicSharedMemorySize, K4B_SMEM);

    kwt_prep<<<1, 256>>>(c1w, c2w);
    k1_kinp_S<<<dim3(128, B), 256>>>(x, im, Wk);
    k2_attn_W2<<<dim3(HEADS), 256>>>(Wq, Wv, Wp, rescale);
    k4a_conv1<<<dim3(128, B), 384, K4A_SMEM>>>();
    k4b_conv2_proj<<<dim3(128, B), 384, K4B_SMEM>>>(fea, bp, out);
}

// round 12
// speedup vs baseline: 1.2875x; 1.0212x over previous
#include <cuda_runtime.h>
#include <math.h>

#define HEADS 8
#define DIM 64
#define DH 64
#define DK 24
#define DHK 3
#define B 4
#define H 128
#define W 128
#define NTOK (H*W)           // 16384

typedef unsigned long long ull;

// ---------------- scratch ---------------------------------------------------
__device__ __align__(16) float g_kinp[B * DK * H * W];  // planar [b][ch][y][x]
__device__ __align__(16) float g_t1[B * DK * H * W];    // gelu(conv1) planar
__device__ __align__(16) float g_SW[2 * B * 24 * 64];   // S then W2

// ---------------- packed f32x2 helpers -------------------------------------
__device__ __forceinline__ ull pack2(float lo, float hi) {
    ull r; asm("mov.b64 %0, {%1,%2};" : "=l"(r) : "f"(lo), "f"(hi)); return r;
}
__device__ __forceinline__ void unpack2(ull v, float& lo, float& hi) {
    asm("mov.b64 {%0,%1}, %2;" : "=f"(lo), "=f"(hi) : "l"(v));
}
__device__ __forceinline__ void fma2(ull& d, ull a, ull b) {
    asm("fma.rn.f32x2 %0, %1, %2, %0;" : "+l"(d) : "l"(a), "l"(b));
}
__device__ __forceinline__ ull add2(ull a, ull b) {
    ull r; asm("add.rn.f32x2 %0, %1, %2;" : "=l"(r) : "l"(a), "l"(b)); return r;
}

__device__ __forceinline__ float gelu_exact(float x) {
    return 0.5f * x * (1.0f + erff(x * 0.70710678118654752f));
}

// ===========================================================================
// K1: k_inp = illu_map @ Wk (planar write) + S[b] += k_inp^T @ x
// grid (128 rows, B) block 256, dynamic smem 49.4KB, 4 blocks/SM.
// S-loop: warp = (j-half of 12, t-quarter of 32); k read as float4 quads
// (broadcast), x as ull pairs -> 160 smem wavefronts/warp (was 640).
// In-block reduction over the 4 t-quarters via the retired x buffer.
// ===========================================================================
#define K1_KS 576                 // k_s: [128][28]
#define K1_BUF 4160               // buf: 8192 floats (im, then x, then partials)
#define K1_SMEM ((4160 + 8192) * 4)

__global__ __launch_bounds__(256, 4) void k1_kinp_S(
    const float* __restrict__ x, const float* __restrict__ im,
    const float* __restrict__ Wk)
{
    extern __shared__ __align__(16) float sm1[];
    float* wk_s = sm1;
    float* k_s = sm1 + K1_KS;      // stride 28 (16B-aligned quads at j0=0/12)
    float* buf = sm1 + K1_BUF;

    const int tid = threadIdx.x;
    const int b = blockIdx.y;
    const int row = blockIdx.x;
    const int t0 = b * NTOK + row * 128;

    for (int i = tid; i < 576; i += 256) wk_s[i] = Wk[i];
    {
        const float* img = im + (size_t)t0 * 24;
        #pragma unroll
        for (int i = tid; i < 3072; i += 256) {
            int tok = i / 24, ci = i - tok * 24;
            buf[tok * 25 + ci] = img[i];
        }
    }
    __syncthreads();

    // k_inp: 2 threads per token (12 out channels each) -> k_s stride 28
    {
        const int tok = tid >> 1;
        const int j0 = (tid & 1) * 12;
        float acc[12];
        #pragma unroll
        for (int j = 0; j < 12; j++) acc[j] = 0.f;
        #pragma unroll 4
        for (int ci = 0; ci < 24; ci++) {
            float inv = buf[tok * 25 + ci];
            const float4* wp4 = (const float4*)&wk_s[ci * 24 + j0];
            float4 w0 = wp4[0], w1 = wp4[1], w2 = wp4[2];
            acc[0] += inv * w0.x; acc[1] += inv * w0.y; acc[2] += inv * w0.z; acc[3] += inv * w0.w;
            acc[4] += inv * w1.x; acc[5] += inv * w1.y; acc[6] += inv * w1.z; acc[7] += inv * w1.w;
            acc[8] += inv * w2.x; acc[9] += inv * w2.y; acc[10] += inv * w2.z; acc[11] += inv * w2.w;
        }
        #pragma unroll
        for (int j = 0; j < 12; j++) k_s[tok * 28 + j0 + j] = acc[j];
    }
    __syncthreads();

    // stage x into buf (overwrites im) + planar k_inp write
    {
        const float4* xg = (const float4*)(x + (size_t)t0 * 64);
        float4* xs4 = (float4*)buf;
        #pragma unroll
        for (int i = tid; i < 2048; i += 256) xs4[i] = xg[i];
    }
    {
        #pragma unroll
        for (int i = tid; i < 3072; i += 256) {
            int ch = i >> 7, xx = i & 127;
            g_kinp[(((size_t)b * 24 + ch) * H + row) * W + xx] = k_s[xx * 28 + ch];
        }
    }
    __syncthreads();

    // S loop: warp w -> jh = w&1 (12 j's), th = w>>1 (32 tokens); lane = c-pair
    const int w = tid >> 5;
    const int cc = tid & 31;
    const int jb = (w & 1) * 12;
    const int tb = (w >> 1) * 32;
    ull acc[12];
    #pragma unroll
    for (int j = 0; j < 12; j++) acc[j] = 0ull;
    {
        const ull* xp = (const ull*)buf;
        #pragma unroll 4
        for (int t = 0; t < 32; t++) {
            const int tt = tb + t;
            ull xv = xp[tt * 32 + cc];
            const float4* kq = (const float4*)(k_s + tt * 28 + jb);
            float4 q0 = kq[0], q1 = kq[1], q2 = kq[2];
            fma2(acc[0], pack2(q0.x, q0.x), xv);
            fma2(acc[1], pack2(q0.y, q0.y), xv);
            fma2(acc[2], pack2(q0.z, q0.z), xv);
            fma2(acc[3], pack2(q0.w, q0.w), xv);
            fma2(acc[4], pack2(q1.x, q1.x), xv);
            fma2(acc[5], pack2(q1.y, q1.y), xv);
            fma2(acc[6], pack2(q1.z, q1.z), xv);
            fma2(acc[7], pack2(q1.w, q1.w), xv);
            fma2(acc[8], pack2(q2.x, q2.x), xv);
            fma2(acc[9], pack2(q2.y, q2.y), xv);
            fma2(acc[10], pack2(q2.z, q2.z), xv);
            fma2(acc[11], pack2(q2.w, q2.w), xv);
        }
    }
    __syncthreads();   // x reads done; buf becomes partial buffer

    ull* pb = (ull*)buf;   // [w 8][j 12][cc 32]
    #pragma unroll
    for (int j = 0; j < 12; j++) pb[w * 384 + j * 32 + cc] = acc[j];
    __syncthreads();

    // reduce the 4 t-quarters, then atomicAdd into g_SW (6 floats/thread)
    {
        float* Sg = g_SW + b * 1536;
        #pragma unroll
        for (int q = 0; q < 3; q++) {
            int idx = tid * 3 + q;            // 0..767 = j*32 + cpair
            int j = idx >> 5, ci = idx & 31;
            int jh = (j >= 12) ? 1 : 0;
            int off = jh * 384 + (j - jh * 12) * 32 + ci;
            ull s = pb[off];
            s = add2(s, pb[off + 2 * 384]);
            s = add2(s, pb[off + 4 * 384]);
            s = add2(s, pb[off + 6 * 384]);
            float lo, hi; unpack2(s, lo, hi);
            atomicAdd(&Sg[j * 64 + ci * 2], lo);
            atomicAdd(&Sg[j * 64 + ci * 2 + 1], hi);
        }
    }
}

// ===========================================================================
// K2: per-head attention + W2. grid (8) block 256. (round 7, proven)
// ===========================================================================
__global__ __launch_bounds__(256) void k2_attn_W2(
    const float* __restrict__ Wq, const float* __restrict__ Wv,
    const float* __restrict__ Wp, const float* __restrict__ rescale)
{
    __shared__ __align__(16) float wqv_s[64 * 65];
    __shared__ float s_S[4 * 3 * 64];
    __shared__ float s_A[4 * 3 * 64];
    __shared__ float s_M[4 * 64 * 3];
    __shared__ float wp_s[3 * 24];

    const int h = blockIdx.x;
    const int tid = threadIdx.x;

    for (int i = tid; i < 4096; i += 256) {
        int c = i >> 6, d = i & 63;
        wqv_s[c * 65 + d] = Wq[c * 512 + h * 64 + d];
    }
    for (int i = tid; i < 768; i += 256) {
        int b = i / 192, rem = i - b * 192;
        s_S[i] = g_SW[b * 1536 + h * 3 * 64 + rem];
    }
    if (tid < 72) {
        int k = tid / 24, o = tid - k * 24;
        wp_s[tid] = Wp[(k * 8 + h) * 24 + o];
    }
    __syncthreads();

    const int b = tid >> 6;
    const int d = tid & 63;
    const float sc = rescale[h] * 0.125f;

    {
        float a0 = 0.f, a1 = 0.f, a2 = 0.f;
        const float* Sb = s_S + b * 192;
        #pragma unroll 8
        for (int c = 0; c < 64; c++) {
            float wq = wqv_s[c * 65 + d];
            a0 += Sb[c] * wq;
            a1 += Sb[64 + c] * wq;
            a2 += Sb[128 + c] * wq;
        }
        s_A[(b * 3 + 0) * 64 + d] = a0 * sc;
        s_A[(b * 3 + 1) * 64 + d] = a1 * sc;
        s_A[(b * 3 + 2) * 64 + d] = a2 * sc;
    }
    __syncthreads();

    {
        const int wid = tid >> 5, lane = tid & 31;
        for (int rowi = wid; rowi < 12; rowi += 8) {
            float v0 = s_A[rowi * 64 + lane];
            float v1 = s_A[rowi * 64 + 32 + lane];
            float m = fmaxf(v0, v1);
            #pragma unroll
            for (int off = 16; off; off >>= 1) m = fmaxf(m, __shfl_xor_sync(~0u, m, off));
            float e0 = __expf(v0 - m), e1 = __expf(v1 - m);
            float s2 = e0 + e1;
            #pragma unroll
            for (int off = 16; off; off >>= 1) s2 += __shfl_xor_sync(~0u, s2, off);
            float inv = 1.0f / s2;
            s_A[rowi * 64 + lane] = e0 * inv;
            s_A[rowi * 64 + 32 + lane] = e1 * inv;
        }
    }
    __syncthreads();

    for (int i = tid; i < 4096; i += 256) {
        int c = i >> 6, dd = i & 63;
        wqv_s[c * 65 + dd] = Wv[c * 512 + h * 64 + dd];
    }
    __syncthreads();

    {
        const int c = tid & 63;
        float m0 = 0.f, m1 = 0.f, m2 = 0.f;
        const float* Ab = s_A + b * 192;
        const float* wvr = wqv_s + c * 65;
        #pragma unroll 8
        for (int dd = 0; dd < 64; dd++) {
            float wv = wvr[dd];
            m0 += wv * Ab[dd];
            m1 += wv * Ab[64 + dd];
            m2 += wv * Ab[128 + dd];
        }
        s_M[(b * 64 + c) * 3 + 0] = m0;
        s_M[(b * 64 + c) * 3 + 1] = m1;
        s_M[(b * 64 + c) * 3 + 2] = m2;
    }
    __syncthreads();

    {
        const int c = tid & 63;
        const float* mrow = &s_M[(b * 64 + c) * 3];
        float m0 = mrow[0], m1 = mrow[1], m2 = mrow[2];
        float* W2g = g_SW + 6144 + b * 1536 + c * 24;
        #pragma unroll
        for (int o = 0; o < 24; o++) {
            float v = m0 * wp_s[o] + m1 * wp_s[24 + o] + m2 * wp_s[48 + o];
            atomicAdd(&W2g[o], v);
        }
    }
}

// ===========================================================================
// Conflict-free conv (round 11, measured): thread = (ocp oc-pair, xseg 4 px).
// Input smem [r][ch][136] (4-float pads), weights splatted ull [tap*24+oc].
// ===========================================================================
__device__ __forceinline__ void conv_row4(
    const float* kin, const ull* wsp, int ocp, int xseg, ull acc[4])
{
    const int g = ocp >> 2;
    const float* kb = kin + (g * 8) * 136 + xseg * 4;
    const int oc0 = ocp * 2;
    #pragma unroll
    for (int i = 0; i < 8; i++) {
        #pragma unroll
        for (int r = 0; r < 3; r++) {
            const float* rp = kb + r * 3264 + i * 136;
            float4 A = *(const float4*)(rp);
            float4 Bv = *(const float4*)(rp + 4);
            float4 C = *(const float4*)(rp + 8);
            ull P0 = pack2(A.w, Bv.x);
            ull P1 = pack2(Bv.x, Bv.y);
            ull P2 = pack2(Bv.y, Bv.z);
            ull P3 = pack2(Bv.z, Bv.w);
            ull P4 = pack2(Bv.w, C.x);
            const int tb = (i * 9 + r * 3) * 24 + oc0;
            {
                ulonglong2 wv = *(const ulonglong2*)&wsp[tb];
                fma2(acc[0], wv.x, P0); fma2(acc[1], wv.x, P2);
                fma2(acc[2], wv.y, P0); fma2(acc[3], wv.y, P2);
            }
            {
                ulonglong2 wv = *(const ulonglong2*)&wsp[tb + 24];
                fma2(acc[0], wv.x, P1); fma2(acc[1], wv.x, P3);
                fma2(acc[2], wv.y, P1); fma2(acc[3], wv.y, P3);
            }
            {
                ulonglong2 wv = *(const ulonglong2*)&wsp[tb + 48];
                fma2(acc[0], wv.x, P2); fma2(acc[1], wv.x, P4);
                fma2(acc[2], wv.y, P2); fma2(acc[3], wv.y, P4);
            }
        }
    }
}

// stage 3 planar rows into kin [3][24][136]; build splatted weights from raw
template<int NT>
__device__ __forceinline__ void stage3w(
    float* kin, ull* wsp, const float* src_base, const float* wraw,
    int b, int y, int tid)
{
    for (int i = tid; i < 1728; i += NT) {
        int oc = i / 72, r2 = i - oc * 72;
        float w = wraw[i];
        wsp[r2 * 24 + oc] = pack2(w, w);
    }
    #pragma unroll
    for (int r = 0; r < 3; r++) {
        int gy = y - 1 + r;
        if ((unsigned)gy < (unsigned)H) {
            const float* sp = src_base + ((size_t)(b * 24) * H + gy) * W;
            for (int i = tid; i < 3072; i += NT) {
                int ch = i >> 7, gx = i & 127;
                kin[r * 3264 + ch * 136 + 4 + gx] = sp[ch * NTOK + gx];
            }
        } else {
            for (int i = tid; i < 3072; i += NT) {
                int ch = i >> 7, gx = i & 127;
                kin[r * 3264 + ch * 136 + 4 + gx] = 0.f;
            }
        }
    }
    for (int t = tid; t < 576; t += NT) {
        int rc = t >> 3, c = t & 7;
        int r = rc / 24, ch = rc - r * 24;
        kin[r * 3264 + ch * 136 + (c < 4 ? c : 128 + c)] = 0.f;
    }
}

// ===========================================================================
// K4A: conv1 + GELU -> g_t1.  grid (128, B), block 384 = ocp(12) x xseg(32).
// ===========================================================================
#define K4_SMEM ((9792 + 3456) * 4)

__global__ __launch_bounds__(384, 3) void k4a_conv1(const float* __restrict__ c1w)
{
    extern __shared__ __align__(16) float s[];
    float* kin = s;
    ull* wsp = (ull*)(s + 9792);

    const int tid = threadIdx.x;
    const int b = blockIdx.y;
    const int y = blockIdx.x;

    stage3w<384>(kin, wsp, g_kinp, c1w, b, y, tid);
    __syncthreads();

    const int ocp = tid >> 5, xseg = tid & 31;
    ull acc[4] = {0ull, 0ull, 0ull, 0ull};
    conv_row4(kin, wsp, ocp, xseg, acc);

    float v[8];
    unpack2(acc[0], v[0], v[1]); unpack2(acc[1], v[2], v[3]);
    unpack2(acc[2], v[4], v[5]); unpack2(acc[3], v[6], v[7]);
    #pragma unroll
    for (int q = 0; q < 8; q++) v[q] = gelu_exact(v[q]);
    const int oc0 = ocp * 2;
    float4* d0 = (float4*)(g_t1 + (((size_t)b * 24 + oc0) * H + y) * W + xseg * 4);
    float4* d1 = (float4*)(g_t1 + (((size_t)b * 24 + oc0 + 1) * H + y) * W + xseg * 4);
    *d0 = make_float4(v[0], v[1], v[2], v[3]);
    *d1 = make_float4(v[4], v[5], v[6], v[7]);
}

// ===========================================================================
// K4B: conv2 (from g_t1) + projection fea@W2+bp + store.
// grid (128, B), block 384. Projection is OUTPUT-SPLIT across lane pairs:
// each half computes 12 of the 24 output channels over all 64 c -> only
// 6 ull accumulators (no spills under the 56-reg cap), no shfl combine.
// ===========================================================================
__global__ __launch_bounds__(384, 3) void k4b_conv2_proj(
    const float* __restrict__ fea, const float* __restrict__ bp,
    const float* __restrict__ c2w, float* __restrict__ out)
{
    extern __shared__ __align__(16) float s[];
    float* t1s = s;
    ull* wsp = (ull*)(s + 9792);

    const int tid = threadIdx.x;
    const int b = blockIdx.y;
    const int y = blockIdx.x;

    stage3w<384>(t1s, wsp, g_t1, c2w, b, y, tid);
    __syncthreads();

    const int ocp = tid >> 5, xseg = tid & 31;
    ull cacc[4] = {0ull, 0ull, 0ull, 0ull};
    conv_row4(t1s, wsp, ocp, xseg, cacc);
    __syncthreads();   // conv reads of t1s/wsp complete

    // conv2 -> c2s (aliases t1s head); W2+bp into wsp region
    float* c2s = t1s;                  // [24][132]
    float* W2s = (float*)wsp;          // 1536 floats
    float* bps = W2s + 1536;
    {
        const int oc0 = ocp * 2;
        float cv[8];
        unpack2(cacc[0], cv[0], cv[1]); unpack2(cacc[1], cv[2], cv[3]);
        unpack2(cacc[2], cv[4], cv[5]); unpack2(cacc[3], cv[6], cv[7]);
        *(float4*)(c2s + oc0 * 132 + xseg * 4) = make_float4(cv[0], cv[1], cv[2], cv[3]);
        *(float4*)(c2s + (oc0 + 1) * 132 + xseg * 4) = make_float4(cv[4], cv[5], cv[6], cv[7]);
    }
    {
        const float* w2g = g_SW + 6144 + b * 1536;
        for (int i = tid; i < 1536; i += 384) W2s[i] = w2g[i];
        if (tid < 24) bps[tid] = bp[tid];
    }
    __syncthreads();

    // projection on threads 0..255: lane pair shares pixel; output-channel split
    if (tid < 256) {
        const int px = tid >> 1;
        const int ob = (tid & 1) * 12;     // this half's 12 output channels
        ull acc[6];
        #pragma unroll
        for (int m = 0; m < 6; m++) acc[m] = 0ull;
        const float4* fea4 = (const float4*)(fea +
            ((size_t)b * NTOK + (size_t)y * W + px) * 64);
        #pragma unroll 4
        for (int c4 = 0; c4 < 16; c4++) {
            float4 f = fea4[c4];
            float fe[4] = {f.x, f.y, f.z, f.w};
            #pragma unroll
            for (int e = 0; e < 4; e++) {
                ull f2 = pack2(fe[e], fe[e]);
                const ulonglong2* wrow =
                    (const ulonglong2*)(W2s + (c4 * 4 + e) * 24 + ob);
                ulonglong2 wa = wrow[0];
                fma2(acc[0], wa.x, f2);
                fma2(acc[1], wa.y, f2);
                ulonglong2 wb = wrow[1];
                fma2(acc[2], wb.x, f2);
                fma2(acc[3], wb.y, f2);
                ulonglong2 wc = wrow[2];
                fma2(acc[4], wc.x, f2);
                fma2(acc[5], wc.y, f2);
            }
        }
        float res[12];
        #pragma unroll
        for (int m = 0; m < 6; m++) {
            float lo, hi; unpack2(acc[m], lo, hi);
            res[2 * m] = lo + bps[ob + 2 * m];
            res[2 * m + 1] = hi + bps[ob + 2 * m + 1];
        }
        #pragma unroll
        for (int ch = 0; ch < 12; ch++)
            res[ch] += c2s[(ob + ch) * 132 + px];
        float4* og = (float4*)(out +
            ((size_t)b * NTOK + (size_t)y * W + px) * 24 + ob);
        og[0] = make_float4(res[0], res[1], res[2], res[3]);
        og[1] = make_float4(res[4], res[5], res[6], res[7]);
        og[2] = make_float4(res[8], res[9], res[10], res[11]);
    }
}

// ===========================================================================
extern "C" void kernel_launch(void* const* d_in, const int* in_sizes, int n_in,
                              void* d_out, int out_size)
{
    const float* x = (const float*)d_in[0];
    const float* fea = (const float*)d_in[1];
    const float* im = (const float*)d_in[2];
    const float* Wq = (const float*)d_in[3];
    const float* Wk = (const float*)d_in[4];
    const float* Wv = (const float*)d_in[5];
    const float* rescale = (const float*)d_in[6];
    const float* Wp = (const float*)d_in[7];
    const float* bp = (const float*)d_in[8];
    const float* c1w = (const float*)d_in[9];
    const float* c2w = (const float*)d_in[10];
    float* out = (float*)d_out;

    cudaFuncSetAttribute(k1_kinp_S,
                         cudaFuncAttributeMaxDynamicSharedMemorySize, K1_SMEM);
    cudaFuncSetAttribute(k4a_conv1,
                         cudaFuncAttributeMaxDynamicSharedMemorySize, K4_SMEM);
    cudaFuncSetAttribute(k4b_conv2_proj,
                         cudaFuncAttributeMaxDynamicSharedMemorySize, K4_SMEM);

    void* swptr = nullptr;
    cudaGetSymbolAddress(&swptr, g_SW);
    cudaMemsetAsync(swptr, 0, sizeof(float) * 2 * B * 24 * 64, 0);

    k1_kinp_S<<<dim3(128, B), 256, K1_SMEM>>>(x, im, Wk);      // kernel 1
    k2_attn_W2<<<dim3(HEADS), 256>>>(Wq, Wv, Wp, rescale);     // kernel 2
    k4a_conv1<<<dim3(128, B), 384, K4_SMEM>>>(c1w);            // kernel 3
    k4b_conv2_proj<<<dim3(128, B), 384, K4_SMEM>>>(fea, bp, c2w, out); // kernel 4 -> profiled
}

// round 13
// speedup vs baseline: 1.5685x; 1.2183x over previous
#include <cuda_runtime.h>
#include <math.h>

#define HEADS 8
#define DIM 64
#define DH 64
#define DK 24
#define DHK 3
#define B 4
#define H 128
#define W 128
#define NTOK (H*W)           // 16384

typedef unsigned long long ull;

// ---------------- scratch ---------------------------------------------------
__device__ __align__(16) float g_kinp[B * DK * H * W];  // planar [b][ch][y][x]
__device__ __align__(16) float g_t1[B * DK * H * W];    // gelu(conv1) planar
__device__ __align__(16) float g_SW[2 * B * 24 * 64];   // S then W2

// ---------------- packed f32x2 helpers -------------------------------------
__device__ __forceinline__ ull pack2(float lo, float hi) {
    ull r; asm("mov.b64 %0, {%1,%2};" : "=l"(r) : "f"(lo), "f"(hi)); return r;
}
__device__ __forceinline__ void unpack2(ull v, float& lo, float& hi) {
    asm("mov.b64 {%0,%1}, %2;" : "=f"(lo), "=f"(hi) : "l"(v));
}
__device__ __forceinline__ void fma2(ull& d, ull a, ull b) {
    asm("fma.rn.f32x2 %0, %1, %2, %0;" : "+l"(d) : "l"(a), "l"(b));
}
__device__ __forceinline__ ull add2(ull a, ull b) {
    ull r; asm("add.rn.f32x2 %0, %1, %2;" : "=l"(r) : "l"(a), "l"(b)); return r;
}

__device__ __forceinline__ float gelu_exact(float x) {
    return 0.5f * x * (1.0f + erff(x * 0.70710678118654752f));
}

// ===========================================================================
// K1: k_inp = illu_map @ Wk (planar write) + S[b] += k_inp^T @ x
// (byte-identical to round 7 - measured 21.5us)
// ===========================================================================
__global__ __launch_bounds__(256, 4) void k1_kinp_S(
    const float* __restrict__ x, const float* __restrict__ im,
    const float* __restrict__ Wk)
{
    __shared__ __align__(16) float wk_s[576];
    __shared__ __align__(16) float k_s[128 * 25];
    __shared__ __align__(16) float buf[128 * 64];   // im_s then x_s

    const int tid = threadIdx.x;
    const int b = blockIdx.y;
    const int row = blockIdx.x;
    const int t0 = b * NTOK + row * 128;

    for (int i = tid; i < 576; i += 256) wk_s[i] = Wk[i];
    {
        const float* img = im + (size_t)t0 * 24;
        #pragma unroll
        for (int i = tid; i < 3072; i += 256) {
            int tok = i / 24, ci = i - tok * 24;
            buf[tok * 25 + ci] = img[i];
        }
    }
    __syncthreads();

    {
        const int tok = tid >> 1;
        const int j0 = (tid & 1) * 12;
        float acc[12];
        #pragma unroll
        for (int j = 0; j < 12; j++) acc[j] = 0.f;
        #pragma unroll 4
        for (int ci = 0; ci < 24; ci++) {
            float inv = buf[tok * 25 + ci];
            const float4* wp4 = (const float4*)&wk_s[ci * 24 + j0];
            float4 w0 = wp4[0], w1 = wp4[1], w2 = wp4[2];
            acc[0] += inv * w0.x; acc[1] += inv * w0.y; acc[2] += inv * w0.z; acc[3] += inv * w0.w;
            acc[4] += inv * w1.x; acc[5] += inv * w1.y; acc[6] += inv * w1.z; acc[7] += inv * w1.w;
            acc[8] += inv * w2.x; acc[9] += inv * w2.y; acc[10] += inv * w2.z; acc[11] += inv * w2.w;
        }
        #pragma unroll
        for (int j = 0; j < 12; j++) k_s[tok * 25 + j0 + j] = acc[j];
    }
    __syncthreads();

    {
        const float4* xg = (const float4*)(x + (size_t)t0 * 64);
        float4* xs4 = (float4*)buf;
        #pragma unroll
        for (int i = tid; i < 2048; i += 256) xs4[i] = xg[i];
    }
    {
        #pragma unroll
        for (int i = tid; i < 3072; i += 256) {
            int ch = i >> 7, xx = i & 127;
            g_kinp[(((size_t)b * 24 + ch) * H + row) * W + xx] = k_s[xx * 25 + ch];
        }
    }
    __syncthreads();

    {
        const int jj = tid >> 5;
        const int cc = tid & 31;
        ull s0 = 0, s1 = 0, s2 = 0;
        const ull* xp = (const ull*)buf;
        #pragma unroll 4
        for (int t = 0; t < 128; t++) {
            ull xv = xp[t * 32 + cc];
            float ka = k_s[t * 25 + jj * 3 + 0];
            float kb = k_s[t * 25 + jj * 3 + 1];
            float kc = k_s[t * 25 + jj * 3 + 2];
            fma2(s0, pack2(ka, ka), xv);
            fma2(s1, pack2(kb, kb), xv);
            fma2(s2, pack2(kc, kc), xv);
        }
        float lo, hi;
        float* Sg = g_SW + b * 1536;
        unpack2(s0, lo, hi);
        atomicAdd(&Sg[(jj * 3 + 0) * 64 + cc * 2], lo);
        atomicAdd(&Sg[(jj * 3 + 0) * 64 + cc * 2 + 1], hi);
        unpack2(s1, lo, hi);
        atomicAdd(&Sg[(jj * 3 + 1) * 64 + cc * 2], lo);
        atomicAdd(&Sg[(jj * 3 + 1) * 64 + cc * 2 + 1], hi);
        unpack2(s2, lo, hi);
        atomicAdd(&Sg[(jj * 3 + 2) * 64 + cc * 2], lo);
        atomicAdd(&Sg[(jj * 3 + 2) * 64 + cc * 2 + 1], hi);
    }
}

// ===========================================================================
// K2: per-head attention + W2. grid (8) block 256. (round 7, proven)
// ===========================================================================
__global__ __launch_bounds__(256) void k2_attn_W2(
    const float* __restrict__ Wq, const float* __restrict__ Wv,
    const float* __restrict__ Wp, const float* __restrict__ rescale)
{
    __shared__ __align__(16) float wqv_s[64 * 65];
    __shared__ float s_S[4 * 3 * 64];
    __shared__ float s_A[4 * 3 * 64];
    __shared__ float s_M[4 * 64 * 3];
    __shared__ float wp_s[3 * 24];

    const int h = blockIdx.x;
    const int tid = threadIdx.x;

    for (int i = tid; i < 4096; i += 256) {
        int c = i >> 6, d = i & 63;
        wqv_s[c * 65 + d] = Wq[c * 512 + h * 64 + d];
    }
    for (int i = tid; i < 768; i += 256) {
        int b = i / 192, rem = i - b * 192;
        s_S[i] = g_SW[b * 1536 + h * 3 * 64 + rem];
    }
    if (tid < 72) {
        int k = tid / 24, o = tid - k * 24;
        wp_s[tid] = Wp[(k * 8 + h) * 24 + o];
    }
    __syncthreads();

    const int b = tid >> 6;
    const int d = tid & 63;
    const float sc = rescale[h] * 0.125f;

    {
        float a0 = 0.f, a1 = 0.f, a2 = 0.f;
        const float* Sb = s_S + b * 192;
        #pragma unroll 8
        for (int c = 0; c < 64; c++) {
            float wq = wqv_s[c * 65 + d];
            a0 += Sb[c] * wq;
            a1 += Sb[64 + c] * wq;
            a2 += Sb[128 + c] * wq;
        }
        s_A[(b * 3 + 0) * 64 + d] = a0 * sc;
        s_A[(b * 3 + 1) * 64 + d] = a1 * sc;
        s_A[(b * 3 + 2) * 64 + d] = a2 * sc;
    }
    __syncthreads();

    {
        const int wid = tid >> 5, lane = tid & 31;
        for (int rowi = wid; rowi < 12; rowi += 8) {
            float v0 = s_A[rowi * 64 + lane];
            float v1 = s_A[rowi * 64 + 32 + lane];
            float m = fmaxf(v0, v1);
            #pragma unroll
            for (int off = 16; off; off >>= 1) m = fmaxf(m, __shfl_xor_sync(~0u, m, off));
            float e0 = __expf(v0 - m), e1 = __expf(v1 - m);
            float s2 = e0 + e1;
            #pragma unroll
            for (int off = 16; off; off >>= 1) s2 += __shfl_xor_sync(~0u, s2, off);
            float inv = 1.0f / s2;
            s_A[rowi * 64 + lane] = e0 * inv;
            s_A[rowi * 64 + 32 + lane] = e1 * inv;
        }
    }
    __syncthreads();

    for (int i = tid; i < 4096; i += 256) {
        int c = i >> 6, dd = i & 63;
        wqv_s[c * 65 + dd] = Wv[c * 512 + h * 64 + dd];
    }
    __syncthreads();

    {
        const int c = tid & 63;
        float m0 = 0.f, m1 = 0.f, m2 = 0.f;
        const float* Ab = s_A + b * 192;
        const float* wvr = wqv_s + c * 65;
        #pragma unroll 8
        for (int dd = 0; dd < 64; dd++) {
            float wv = wvr[dd];
            m0 += wv * Ab[dd];
            m1 += wv * Ab[64 + dd];
            m2 += wv * Ab[128 + dd];
        }
        s_M[(b * 64 + c) * 3 + 0] = m0;
        s_M[(b * 64 + c) * 3 + 1] = m1;
        s_M[(b * 64 + c) * 3 + 2] = m2;
    }
    __syncthreads();

    {
        const int c = tid & 63;
        const float* mrow = &s_M[(b * 64 + c) * 3];
        float m0 = mrow[0], m1 = mrow[1], m2 = mrow[2];
        float* W2g = g_SW + 6144 + b * 1536 + c * 24;
        #pragma unroll
        for (int o = 0; o < 24; o++) {
            float v = m0 * wp_s[o] + m1 * wp_s[24 + o] + m2 * wp_s[48 + o];
            atomicAdd(&W2g[o], v);
        }
    }
}

// ===========================================================================
// LDG+shfl conv: warp = one full image row (32 lanes x 4 px), thread =
// (ocp oc-pair, lane). Input read directly from planar global via coalesced
// 512B LDG.128; +/-1 px halo via shfl with natural zeros at the image border.
// Out-of-image rows skipped (block-uniform). Weights splatted in smem.
// ===========================================================================
__device__ __forceinline__ void conv_ldg(
    const float* __restrict__ src, const ull* wsp,
    int b, int y, int ocp, int lane, ull acc[4])
{
    const int g = ocp >> 2;
    const int oc0 = ocp * 2;
    #pragma unroll
    for (int r = 0; r < 3; r++) {
        const int gy = y - 1 + r;
        if ((unsigned)gy >= (unsigned)H) continue;
        const float* rowbase = src + (((size_t)b * 24 + g * 8) * H + gy) * W + lane * 4;
        #pragma unroll
        for (int i = 0; i < 8; i++) {
            float4 Bv = __ldg((const float4*)(rowbase + i * NTOK));
            float left = __shfl_up_sync(~0u, Bv.w, 1);
            if (lane == 0) left = 0.f;
            float right = __shfl_down_sync(~0u, Bv.x, 1);
            if (lane == 31) right = 0.f;
            ull P0 = pack2(left, Bv.x);
            ull P1 = pack2(Bv.x, Bv.y);
            ull P2 = pack2(Bv.y, Bv.z);
            ull P3 = pack2(Bv.z, Bv.w);
            ull P4 = pack2(Bv.w, right);
            const int tb = (i * 9 + r * 3) * 24 + oc0;
            {
                ulonglong2 wv = *(const ulonglong2*)&wsp[tb];
                fma2(acc[0], wv.x, P0); fma2(acc[1], wv.x, P2);
                fma2(acc[2], wv.y, P0); fma2(acc[3], wv.y, P2);
            }
            {
                ulonglong2 wv = *(const ulonglong2*)&wsp[tb + 24];
                fma2(acc[0], wv.x, P1); fma2(acc[1], wv.x, P3);
                fma2(acc[2], wv.y, P1); fma2(acc[3], wv.y, P3);
            }
            {
                ulonglong2 wv = *(const ulonglong2*)&wsp[tb + 48];
                fma2(acc[0], wv.x, P2); fma2(acc[1], wv.x, P4);
                fma2(acc[2], wv.y, P2); fma2(acc[3], wv.y, P4);
            }
        }
    }
}

// ===========================================================================
// K4A: conv1 + GELU -> g_t1.  grid (128, B), block 384 = ocp(12) x lane(32).
// smem: splatted weights only (13.8 KB). One __syncthreads total.
// ===========================================================================
__global__ __launch_bounds__(384, 3) void k4a_conv1(const float* __restrict__ c1w)
{
    __shared__ __align__(16) ull wsp[1728];

    const int tid = threadIdx.x;
    const int b = blockIdx.y;
    const int y = blockIdx.x;

    for (int i = tid; i < 1728; i += 384) {
        int oc = i / 72, r2 = i - oc * 72;
        float w = c1w[i];
        wsp[r2 * 24 + oc] = pack2(w, w);
    }
    __syncthreads();

    const int ocp = tid >> 5, lane = tid & 31;
    ull acc[4] = {0ull, 0ull, 0ull, 0ull};
    conv_ldg(g_kinp, wsp, b, y, ocp, lane, acc);

    float v[8];
    unpack2(acc[0], v[0], v[1]); unpack2(acc[1], v[2], v[3]);   // oc0 px0..3
    unpack2(acc[2], v[4], v[5]); unpack2(acc[3], v[6], v[7]);   // oc1 px0..3
    #pragma unroll
    for (int q = 0; q < 8; q++) v[q] = gelu_exact(v[q]);
    const int oc0 = ocp * 2;
    float4* d0 = (float4*)(g_t1 + (((size_t)b * 24 + oc0) * H + y) * W + lane * 4);
    float4* d1 = (float4*)(g_t1 + (((size_t)b * 24 + oc0 + 1) * H + y) * W + lane * 4);
    *d0 = make_float4(v[0], v[1], v[2], v[3]);
    *d1 = make_float4(v[4], v[5], v[6], v[7]);
}

// ===========================================================================
// K4B: conv2 (LDG from g_t1, L2-hot) + projection fea@W2+bp + store.
// grid (128, B), block 384. smem: wsp 13.8KB + c2s 12.7KB + W2s 6KB + bps.
// Projection: lane pair shares pixel, output-channel split (R12, proven).
// ===========================================================================
__global__ __launch_bounds__(384, 3) void k4b_conv2_proj(
    const float* __restrict__ fea, const float* __restrict__ bp,
    const float* __restrict__ c2w, float* __restrict__ out)
{
    __shared__ __align__(16) ull wsp[1728];
    __shared__ __align__(16) float c2s[24 * 132];
    __shared__ __align__(16) float W2s[1536];
    __shared__ float bps[32];

    const int tid = threadIdx.x;
    const int b = blockIdx.y;
    const int y = blockIdx.x;

    for (int i = tid; i < 1728; i += 384) {
        int oc = i / 72, r2 = i - oc * 72;
        float w = c2w[i];
        wsp[r2 * 24 + oc] = pack2(w, w);
    }
    {
        const float* w2g = g_SW + 6144 + b * 1536;
        for (int i = tid; i < 1536; i += 384) W2s[i] = w2g[i];
    }
    if (tid < 24) bps[tid] = bp[tid];
    __syncthreads();

    const int ocp = tid >> 5, lane = tid & 31;
    ull cacc[4] = {0ull, 0ull, 0ull, 0ull};
    conv_ldg(g_t1, wsp, b, y, ocp, lane, cacc);

    {
        const int oc0 = ocp * 2;
        float cv[8];
        unpack2(cacc[0], cv[0], cv[1]); unpack2(cacc[1], cv[2], cv[3]);
        unpack2(cacc[2], cv[4], cv[5]); unpack2(cacc[3], cv[6], cv[7]);
        *(float4*)(c2s + oc0 * 132 + lane * 4) = make_float4(cv[0], cv[1], cv[2], cv[3]);
        *(float4*)(c2s + (oc0 + 1) * 132 + lane * 4) = make_float4(cv[4], cv[5], cv[6], cv[7]);
    }
    __syncthreads();

    // projection on threads 0..255: lane pair shares pixel; output split
    if (tid < 256) {
        const int px = tid >> 1;
        const int ob = (tid & 1) * 12;
        ull acc[6];
        #pragma unroll
        for (int m = 0; m < 6; m++) acc[m] = 0ull;
        const float4* fea4 = (const float4*)(fea +
            ((size_t)b * NTOK + (size_t)y * W + px) * 64);
        #pragma unroll 4
        for (int c4 = 0; c4 < 16; c4++) {
            float4 f = fea4[c4];
            float fe[4] = {f.x, f.y, f.z, f.w};
            #pragma unroll
            for (int e = 0; e < 4; e++) {
                ull f2 = pack2(fe[e], fe[e]);
                const ulonglong2* wrow =
                    (const ulonglong2*)(W2s + (c4 * 4 + e) * 24 + ob);
                ulonglong2 wa = wrow[0];
                fma2(acc[0], wa.x, f2);
                fma2(acc[1], wa.y, f2);
                ulonglong2 wb = wrow[1];
                fma2(acc[2], wb.x, f2);
                fma2(acc[3], wb.y, f2);
                ulonglong2 wc = wrow[2];
                fma2(acc[4], wc.x, f2);
                fma2(acc[5], wc.y, f2);
            }
        }
        float res[12];
        #pragma unroll
        for (int m = 0; m < 6; m++) {
            float lo, hi; unpack2(acc[m], lo, hi);
            res[2 * m] = lo + bps[ob + 2 * m];
            res[2 * m + 1] = hi + bps[ob + 2 * m + 1];
        }
        #pragma unroll
        for (int ch = 0; ch < 12; ch++)
            res[ch] += c2s[(ob + ch) * 132 + px];
        float4* og = (float4*)(out +
            ((size_t)b * NTOK + (size_t)y * W + px) * 24 + ob);
        og[0] = make_float4(res[0], res[1], res[2], res[3]);
        og[1] = make_float4(res[4], res[5], res[6], res[7]);
        og[2] = make_float4(res[8], res[9], res[10], res[11]);
    }
}

// ===========================================================================
extern "C" void kernel_launch(void* const* d_in, const int* in_sizes, int n_in,
                              void* d_out, int out_size)
{
    const float* x = (const float*)d_in[0];
    const float* fea = (const float*)d_in[1];
    const float* im = (const float*)d_in[2];
    const float* Wq = (const float*)d_in[3];
    const float* Wk = (const float*)d_in[4];
    const float* Wv = (const float*)d_in[5];
    const float* rescale = (const float*)d_in[6];
    const float* Wp = (const float*)d_in[7];
    const float* bp = (const float*)d_in[8];
    const float* c1w = (const float*)d_in[9];
    const float* c2w = (const float*)d_in[10];
    float* out = (float*)d_out;

    void* swptr = nullptr;
    cudaGetSymbolAddress(&swptr, g_SW);
    cudaMemsetAsync(swptr, 0, sizeof(float) * 2 * B * 24 * 64, 0);

    k1_kinp_S<<<dim3(128, B), 256>>>(x, im, Wk);                 // kernel 1
    k2_attn_W2<<<dim3(HEADS), 256>>>(Wq, Wv, Wp, rescale);       // kernel 2
    k4a_conv1<<<dim3(128, B), 384>>>(c1w);                       // kernel 3
    k4b_conv2_proj<<<dim3(128, B), 384>>>(fea, bp, c2w, out);    // kernel 4 -> profiled
}

// round 14
// speedup vs baseline: 1.6766x; 1.0689x over previous
#include <cuda_runtime.h>
#include <math.h>

#define HEADS 8
#define DIM 64
#define DH 64
#define DK 24
#define DHK 3
#define B 4
#define H 128
#define W 128
#define NTOK (H*W)           // 16384

typedef unsigned long long ull;

// ---------------- scratch ---------------------------------------------------
__device__ __align__(16) float g_kinp[B * DK * H * W];  // planar [b][ch][y][x]
__device__ __align__(16) float g_t1[B * DK * H * W];    // gelu(conv1) planar
__device__ __align__(16) float g_SW[2 * B * 24 * 64];   // S then W2 (zero-init)

// ---------------- packed f32x2 helpers -------------------------------------
__device__ __forceinline__ ull pack2(float lo, float hi) {
    ull r; asm("mov.b64 %0, {%1,%2};" : "=l"(r) : "f"(lo), "f"(hi)); return r;
}
__device__ __forceinline__ void unpack2(ull v, float& lo, float& hi) {
    asm("mov.b64 {%0,%1}, %2;" : "=f"(lo), "=f"(hi) : "l"(v));
}
__device__ __forceinline__ void fma2(ull& d, ull a, ull b) {
    asm("fma.rn.f32x2 %0, %1, %2, %0;" : "+l"(d) : "l"(a), "l"(b));
}
__device__ __forceinline__ ull add2(ull a, ull b) {
    ull r; asm("add.rn.f32x2 %0, %1, %2;" : "=l"(r) : "l"(a), "l"(b)); return r;
}

__device__ __forceinline__ float gelu_exact(float x) {
    return 0.5f * x * (1.0f + erff(x * 0.70710678118654752f));
}

// ===========================================================================
// K1: k_inp = illu_map @ Wk (planar write) + S[b] += k_inp^T @ x
// (round 7 body, measured 21.5us) + zero the W2 region for this replay
// (k2-role adds into W2 only after k1 completes; previous replay's k4b has
// already consumed it).
// ===========================================================================
__global__ __launch_bounds__(256, 4) void k1_kinp_S(
    const float* __restrict__ x, const float* __restrict__ im,
    const float* __restrict__ Wk)
{
    __shared__ __align__(16) float wk_s[576];
    __shared__ __align__(16) float k_s[128 * 25];
    __shared__ __align__(16) float buf[128 * 64];   // im_s then x_s

    const int tid = threadIdx.x;
    const int b = blockIdx.y;
    const int row = blockIdx.x;
    const int t0 = b * NTOK + row * 128;

    // zero W2 slice (12 floats per block, 512 blocks cover 6144 floats)
    {
        int bid = blockIdx.y * 128 + blockIdx.x;
        if (tid < 12) g_SW[6144 + bid * 12 + tid] = 0.f;
    }

    for (int i = tid; i < 576; i += 256) wk_s[i] = Wk[i];
    {
        const float* img = im + (size_t)t0 * 24;
        #pragma unroll
        for (int i = tid; i < 3072; i += 256) {
            int tok = i / 24, ci = i - tok * 24;
            buf[tok * 25 + ci] = img[i];
        }
    }
    __syncthreads();

    {
        const int tok = tid >> 1;
        const int j0 = (tid & 1) * 12;
        float acc[12];
        #pragma unroll
        for (int j = 0; j < 12; j++) acc[j] = 0.f;
        #pragma unroll 4
        for (int ci = 0; ci < 24; ci++) {
            float inv = buf[tok * 25 + ci];
            const float4* wp4 = (const float4*)&wk_s[ci * 24 + j0];
            float4 w0 = wp4[0], w1 = wp4[1], w2 = wp4[2];
            acc[0] += inv * w0.x; acc[1] += inv * w0.y; acc[2] += inv * w0.z; acc[3] += inv * w0.w;
            acc[4] += inv * w1.x; acc[5] += inv * w1.y; acc[6] += inv * w1.z; acc[7] += inv * w1.w;
            acc[8] += inv * w2.x; acc[9] += inv * w2.y; acc[10] += inv * w2.z; acc[11] += inv * w2.w;
        }
        #pragma unroll
        for (int j = 0; j < 12; j++) k_s[tok * 25 + j0 + j] = acc[j];
    }
    __syncthreads();

    {
        const float4* xg = (const float4*)(x + (size_t)t0 * 64);
        float4* xs4 = (float4*)buf;
        #pragma unroll
        for (int i = tid; i < 2048; i += 256) xs4[i] = xg[i];
    }
    {
        #pragma unroll
        for (int i = tid; i < 3072; i += 256) {
            int ch = i >> 7, xx = i & 127;
            g_kinp[(((size_t)b * 24 + ch) * H + row) * W + xx] = k_s[xx * 25 + ch];
        }
    }
    __syncthreads();

    {
        const int jj = tid >> 5;
        const int cc = tid & 31;
        ull s0 = 0, s1 = 0, s2 = 0;
        const ull* xp = (const ull*)buf;
        #pragma unroll 4
        for (int t = 0; t < 128; t++) {
            ull xv = xp[t * 32 + cc];
            float ka = k_s[t * 25 + jj * 3 + 0];
            float kb = k_s[t * 25 + jj * 3 + 1];
            float kc = k_s[t * 25 + jj * 3 + 2];
            fma2(s0, pack2(ka, ka), xv);
            fma2(s1, pack2(kb, kb), xv);
            fma2(s2, pack2(kc, kc), xv);
        }
        float lo, hi;
        float* Sg = g_SW + b * 1536;
        unpack2(s0, lo, hi);
        atomicAdd(&Sg[(jj * 3 + 0) * 64 + cc * 2], lo);
        atomicAdd(&Sg[(jj * 3 + 0) * 64 + cc * 2 + 1], hi);
        unpack2(s1, lo, hi);
        atomicAdd(&Sg[(jj * 3 + 1) * 64 + cc * 2], lo);
        atomicAdd(&Sg[(jj * 3 + 1) * 64 + cc * 2 + 1], hi);
        unpack2(s2, lo, hi);
        atomicAdd(&Sg[(jj * 3 + 2) * 64 + cc * 2], lo);
        atomicAdd(&Sg[(jj * 3 + 2) * 64 + cc * 2 + 1], hi);
    }
}

// ===========================================================================
// LDG+shfl conv (round 13, measured): warp = full image row (32 lanes x 4 px),
// thread = (ocp oc-pair, lane). Halo via shfl, border zeros natural.
// ===========================================================================
__device__ __forceinline__ void conv_ldg(
    const float* __restrict__ src, const ull* wsp,
    int b, int y, int ocp, int lane, ull acc[4])
{
    const int g = ocp >> 2;
    const int oc0 = ocp * 2;
    #pragma unroll
    for (int r = 0; r < 3; r++) {
        const int gy = y - 1 + r;
        if ((unsigned)gy >= (unsigned)H) continue;
        const float* rowbase = src + (((size_t)b * 24 + g * 8) * H + gy) * W + lane * 4;
        #pragma unroll
        for (int i = 0; i < 8; i++) {
            float4 Bv = __ldg((const float4*)(rowbase + i * NTOK));
            float left = __shfl_up_sync(~0u, Bv.w, 1);
            if (lane == 0) left = 0.f;
            float right = __shfl_down_sync(~0u, Bv.x, 1);
            if (lane == 31) right = 0.f;
            ull P0 = pack2(left, Bv.x);
            ull P1 = pack2(Bv.x, Bv.y);
            ull P2 = pack2(Bv.y, Bv.z);
            ull P3 = pack2(Bv.z, Bv.w);
            ull P4 = pack2(Bv.w, right);
            const int tb = (i * 9 + r * 3) * 24 + oc0;
            {
                ulonglong2 wv = *(const ulonglong2*)&wsp[tb];
                fma2(acc[0], wv.x, P0); fma2(acc[1], wv.x, P2);
                fma2(acc[2], wv.y, P0); fma2(acc[3], wv.y, P2);
            }
            {
                ulonglong2 wv = *(const ulonglong2*)&wsp[tb + 24];
                fma2(acc[0], wv.x, P1); fma2(acc[1], wv.x, P3);
                fma2(acc[2], wv.y, P1); fma2(acc[3], wv.y, P3);
            }
            {
                ulonglong2 wv = *(const ulonglong2*)&wsp[tb + 48];
                fma2(acc[0], wv.x, P2); fma2(acc[1], wv.x, P4);
                fma2(acc[2], wv.y, P2); fma2(acc[3], wv.y, P4);
            }
        }
    }
}

// ===========================================================================
// K4A+K2 merged: grid (129, B), block 384.
//  blockIdx.x < 128 : conv1 + GELU -> g_t1 (round 13 conv role)
//  blockIdx.x == 128: attention role for heads (2*b, 2*b+1), runs
//                     concurrently with the conv blocks (depends only on k1).
//                     Zeroes its own S rows after staging (for next replay).
// smem union: conv wsp ull[1728] (13.8KB)  |  k2 buffers (26.1KB)
// ===========================================================================
__global__ __launch_bounds__(384, 3) void k4a_conv1_k2(
    const float* __restrict__ c1w,
    const float* __restrict__ Wq, const float* __restrict__ Wv,
    const float* __restrict__ Wp, const float* __restrict__ rescale)
{
    __shared__ __align__(16) float smu[6536];
    const int tid = threadIdx.x;

    if (blockIdx.x < 128) {
        // ---- conv role ----
        ull* wsp = (ull*)smu;
        const int b = blockIdx.y;
        const int y = blockIdx.x;

        for (int i = tid; i < 1728; i += 384) {
            int oc = i / 72, r2 = i - oc * 72;
            float w = c1w[i];
            wsp[r2 * 24 + oc] = pack2(w, w);
        }
        __syncthreads();

        const int ocp = tid >> 5, lane = tid & 31;
        ull acc[4] = {0ull, 0ull, 0ull, 0ull};
        conv_ldg(g_kinp, wsp, b, y, ocp, lane, acc);

        float v[8];
        unpack2(acc[0], v[0], v[1]); unpack2(acc[1], v[2], v[3]);
        unpack2(acc[2], v[4], v[5]); unpack2(acc[3], v[6], v[7]);
        #pragma unroll
        for (int q = 0; q < 8; q++) v[q] = gelu_exact(v[q]);
        const int oc0 = ocp * 2;
        float4* d0 = (float4*)(g_t1 + (((size_t)b * 24 + oc0) * H + y) * W + lane * 4);
        float4* d1 = (float4*)(g_t1 + (((size_t)b * 24 + oc0 + 1) * H + y) * W + lane * 4);
        *d0 = make_float4(v[0], v[1], v[2], v[3]);
        *d1 = make_float4(v[4], v[5], v[6], v[7]);
        return;
    }

    // ---- attention role: two heads sequentially ----
    float* wqv_s = smu;            // [64][65]
    float* s_S   = smu + 4160;     // [4][3][64]
    float* s_A   = smu + 4928;     // [4][3][64]
    float* s_M   = smu + 5696;     // [4*64][3]
    float* wp_s  = smu + 6464;     // [3][24]

    for (int hh = 0; hh < 2; hh++) {
        const int h = blockIdx.y * 2 + hh;

        for (int i = tid; i < 4096; i += 384) {
            int c = i >> 6, d = i & 63;
            wqv_s[c * 65 + d] = Wq[c * 512 + h * 64 + d];
        }
        for (int i = tid; i < 768; i += 384) {
            int b2 = i / 192, rem = i - b2 * 192;
            s_S[i] = g_SW[b2 * 1536 + h * 3 * 64 + rem];
        }
        if (tid < 72) {
            int k = tid / 24, o = tid - k * 24;
            wp_s[tid] = Wp[(k * 8 + h) * 24 + o];
        }
        __syncthreads();

        // zero these S rows for the next replay (staged copy already in smem)
        for (int i = tid; i < 768; i += 384) {
            int b2 = i / 192, rem = i - b2 * 192;
            g_SW[b2 * 1536 + h * 3 * 64 + rem] = 0.f;
        }

        const int b = tid >> 6;
        const int d = tid & 63;
        const float sc = rescale[h] * 0.125f;

        if (tid < 256) {
            float a0 = 0.f, a1 = 0.f, a2 = 0.f;
            const float* Sb = s_S + b * 192;
            #pragma unroll 8
            for (int c = 0; c < 64; c++) {
                float wq = wqv_s[c * 65 + d];
                a0 += Sb[c] * wq;
                a1 += Sb[64 + c] * wq;
                a2 += Sb[128 + c] * wq;
            }
            s_A[(b * 3 + 0) * 64 + d] = a0 * sc;
            s_A[(b * 3 + 1) * 64 + d] = a1 * sc;
            s_A[(b * 3 + 2) * 64 + d] = a2 * sc;
        }
        __syncthreads();

        if (tid < 256) {
            const int wid = tid >> 5, lane = tid & 31;
            for (int rowi = wid; rowi < 12; rowi += 8) {
                float v0 = s_A[rowi * 64 + lane];
                float v1 = s_A[rowi * 64 + 32 + lane];
                float m = fmaxf(v0, v1);
                #pragma unroll
                for (int off = 16; off; off >>= 1) m = fmaxf(m, __shfl_xor_sync(~0u, m, off));
                float e0 = __expf(v0 - m), e1 = __expf(v1 - m);
                float s2 = e0 + e1;
                #pragma unroll
                for (int off = 16; off; off >>= 1) s2 += __shfl_xor_sync(~0u, s2, off);
                float inv = 1.0f / s2;
                s_A[rowi * 64 + lane] = e0 * inv;
                s_A[rowi * 64 + 32 + lane] = e1 * inv;
            }
        }
        __syncthreads();

        for (int i = tid; i < 4096; i += 384) {
            int c = i >> 6, dd = i & 63;
            wqv_s[c * 65 + dd] = Wv[c * 512 + h * 64 + dd];
        }
        __syncthreads();

        if (tid < 256) {
            const int c = tid & 63;
            float m0 = 0.f, m1 = 0.f, m2 = 0.f;
            const float* Ab = s_A + b * 192;
            const float* wvr = wqv_s + c * 65;
            #pragma unroll 8
            for (int dd = 0; dd < 64; dd++) {
                float wv = wvr[dd];
                m0 += wv * Ab[dd];
                m1 += wv * Ab[64 + dd];
                m2 += wv * Ab[128 + dd];
            }
            s_M[(b * 64 + c) * 3 + 0] = m0;
            s_M[(b * 64 + c) * 3 + 1] = m1;
            s_M[(b * 64 + c) * 3 + 2] = m2;
        }
        __syncthreads();

        if (tid < 256) {
            const int c = tid & 63;
            const float* mrow = &s_M[(b * 64 + c) * 3];
            float m0 = mrow[0], m1 = mrow[1], m2 = mrow[2];
            float* W2g = g_SW + 6144 + b * 1536 + c * 24;
            #pragma unroll
            for (int o = 0; o < 24; o++) {
                float v = m0 * wp_s[o] + m1 * wp_s[24 + o] + m2 * wp_s[48 + o];
                atomicAdd(&W2g[o], v);
            }
        }
        __syncthreads();   // smem reused next head
    }
}

// ===========================================================================
// K4B: conv2 (LDG from g_t1, L2-hot) + projection fea@W2+bp + store.
// (round 13 body, measured 28.8us)
// ===========================================================================
__global__ __launch_bounds__(384, 3) void k4b_conv2_proj(
    const float* __restrict__ fea, const float* __restrict__ bp,
    const float* __restrict__ c2w, float* __restrict__ out)
{
    __shared__ __align__(16) ull wsp[1728];
    __shared__ __align__(16) float c2s[24 * 132];
    __shared__ __align__(16) float W2s[1536];
    __shared__ float bps[32];

    const int tid = threadIdx.x;
    const int b = blockIdx.y;
    const int y = blockIdx.x;

    for (int i = tid; i < 1728; i += 384) {
        int oc = i / 72, r2 = i - oc * 72;
        float w = c2w[i];
        wsp[r2 * 24 + oc] = pack2(w, w);
    }
    {
        const float* w2g = g_SW + 6144 + b * 1536;
        for (int i = tid; i < 1536; i += 384) W2s[i] = w2g[i];
    }
    if (tid < 24) bps[tid] = bp[tid];
    __syncthreads();

    const int ocp = tid >> 5, lane = tid & 31;
    ull cacc[4] = {0ull, 0ull, 0ull, 0ull};
    conv_ldg(g_t1, wsp, b, y, ocp, lane, cacc);

    {
        const int oc0 = ocp * 2;
        float cv[8];
        unpack2(cacc[0], cv[0], cv[1]); unpack2(cacc[1], cv[2], cv[3]);
        unpack2(cacc[2], cv[4], cv[5]); unpack2(cacc[3], cv[6], cv[7]);
        *(float4*)(c2s + oc0 * 132 + lane * 4) = make_float4(cv[0], cv[1], cv[2], cv[3]);
        *(float4*)(c2s + (oc0 + 1) * 132 + lane * 4) = make_float4(cv[4], cv[5], cv[6], cv[7]);
    }
    __syncthreads();

    if (tid < 256) {
        const int px = tid >> 1;
        const int ob = (tid & 1) * 12;
        ull acc[6];
        #pragma unroll
        for (int m = 0; m < 6; m++) acc[m] = 0ull;
        const float4* fea4 = (const float4*)(fea +
            ((size_t)b * NTOK + (size_t)y * W + px) * 64);
        #pragma unroll 4
        for (int c4 = 0; c4 < 16; c4++) {
            float4 f = fea4[c4];
            float fe[4] = {f.x, f.y, f.z, f.w};
            #pragma unroll
            for (int e = 0; e < 4; e++) {
                ull f2 = pack2(fe[e], fe[e]);
                const ulonglong2* wrow =
                    (const ulonglong2*)(W2s + (c4 * 4 + e) * 24 + ob);
                ulonglong2 wa = wrow[0];
                fma2(acc[0], wa.x, f2);
                fma2(acc[1], wa.y, f2);
                ulonglong2 wb = wrow[1];
                fma2(acc[2], wb.x, f2);
                fma2(acc[3], wb.y, f2);
                ulonglong2 wc = wrow[2];
                fma2(acc[4], wc.x, f2);
                fma2(acc[5], wc.y, f2);
            }
        }
        float res[12];
        #pragma unroll
        for (int m = 0; m < 6; m++) {
            float lo, hi; unpack2(acc[m], lo, hi);
            res[2 * m] = lo + bps[ob + 2 * m];
            res[2 * m + 1] = hi + bps[ob + 2 * m + 1];
        }
        #pragma unroll
        for (int ch = 0; ch < 12; ch++)
            res[ch] += c2s[(ob + ch) * 132 + px];
        float4* og = (float4*)(out +
            ((size_t)b * NTOK + (size_t)y * W + px) * 24 + ob);
        og[0] = make_float4(res[0], res[1], res[2], res[3]);
        og[1] = make_float4(res[4], res[5], res[6], res[7]);
        og[2] = make_float4(res[8], res[9], res[10], res[11]);
    }
}

// ===========================================================================
extern "C" void kernel_launch(void* const* d_in, const int* in_sizes, int n_in,
                              void* d_out, int out_size)
{
    const float* x = (const float*)d_in[0];
    const float* fea = (const float*)d_in[1];
    const float* im = (const float*)d_in[2];
    const float* Wq = (const float*)d_in[3];
    const float* Wk = (const float*)d_in[4];
    const float* Wv = (const float*)d_in[5];
    const float* rescale = (const float*)d_in[6];
    const float* Wp = (const float*)d_in[7];
    const float* bp = (const float*)d_in[8];
    const float* c1w = (const float*)d_in[9];
    const float* c2w = (const float*)d_in[10];
    float* out = (float*)d_out;

    k1_kinp_S<<<dim3(128, B), 256>>>(x, im, Wk);
    k4a_conv1_k2<<<dim3(129, B), 384>>>(c1w, Wq, Wv, Wp, rescale);
    k4b_conv2_proj<<<dim3(128, B), 384>>>(fea, bp, c2w, out);
}

// round 15
// speedup vs baseline: 1.7693x; 1.0553x over previous
#include <cuda_runtime.h>
#include <math.h>

#define HEADS 8
#define DIM 64
#define DH 64
#define DK 24
#define DHK 3
#define B 4
#define H 128
#define W 128
#define NTOK (H*W)           // 16384

typedef unsigned long long ull;

// ---------------- scratch ---------------------------------------------------
__device__ __align__(16) float g_kinp[B * DK * H * W];  // planar [b][ch][y][x]
__device__ __align__(16) float g_t1[B * DK * H * W];    // gelu(conv1) planar
__device__ __align__(16) float g_SW[2 * B * 24 * 64];   // S then W2 (zero-init)

// ---------------- packed f32x2 helpers -------------------------------------
__device__ __forceinline__ ull pack2(float lo, float hi) {
    ull r; asm("mov.b64 %0, {%1,%2};" : "=l"(r) : "f"(lo), "f"(hi)); return r;
}
__device__ __forceinline__ void unpack2(ull v, float& lo, float& hi) {
    asm("mov.b64 {%0,%1}, %2;" : "=f"(lo), "=f"(hi) : "l"(v));
}
__device__ __forceinline__ void fma2(ull& d, ull a, ull b) {
    asm("fma.rn.f32x2 %0, %1, %2, %0;" : "+l"(d) : "l"(a), "l"(b));
}
__device__ __forceinline__ ull add2(ull a, ull b) {
    ull r; asm("add.rn.f32x2 %0, %1, %2;" : "=l"(r) : "l"(a), "l"(b)); return r;
}

__device__ __forceinline__ float gelu_exact(float x) {
    return 0.5f * x * (1.0f + erff(x * 0.70710678118654752f));
}

// ===========================================================================
// K1: k_inp = illu_map @ Wk (planar write) + S[b] += k_inp^T @ x
// (round 7 body, measured) + zero the W2 region for this replay.
// ===========================================================================
__global__ __launch_bounds__(256, 4) void k1_kinp_S(
    const float* __restrict__ x, const float* __restrict__ im,
    const float* __restrict__ Wk)
{
    __shared__ __align__(16) float wk_s[576];
    __shared__ __align__(16) float k_s[128 * 25];
    __shared__ __align__(16) float buf[128 * 64];   // im_s then x_s

    const int tid = threadIdx.x;
    const int b = blockIdx.y;
    const int row = blockIdx.x;
    const int t0 = b * NTOK + row * 128;

    {
        int bid = blockIdx.y * 128 + blockIdx.x;
        if (tid < 12) g_SW[6144 + bid * 12 + tid] = 0.f;
    }

    for (int i = tid; i < 576; i += 256) wk_s[i] = Wk[i];
    {
        const float* img = im + (size_t)t0 * 24;
        #pragma unroll
        for (int i = tid; i < 3072; i += 256) {
            int tok = i / 24, ci = i - tok * 24;
            buf[tok * 25 + ci] = img[i];
        }
    }
    __syncthreads();

    {
        const int tok = tid >> 1;
        const int j0 = (tid & 1) * 12;
        float acc[12];
        #pragma unroll
        for (int j = 0; j < 12; j++) acc[j] = 0.f;
        #pragma unroll 4
        for (int ci = 0; ci < 24; ci++) {
            float inv = buf[tok * 25 + ci];
            const float4* wp4 = (const float4*)&wk_s[ci * 24 + j0];
            float4 w0 = wp4[0], w1 = wp4[1], w2 = wp4[2];
            acc[0] += inv * w0.x; acc[1] += inv * w0.y; acc[2] += inv * w0.z; acc[3] += inv * w0.w;
            acc[4] += inv * w1.x; acc[5] += inv * w1.y; acc[6] += inv * w1.z; acc[7] += inv * w1.w;
            acc[8] += inv * w2.x; acc[9] += inv * w2.y; acc[10] += inv * w2.z; acc[11] += inv * w2.w;
        }
        #pragma unroll
        for (int j = 0; j < 12; j++) k_s[tok * 25 + j0 + j] = acc[j];
    }
    __syncthreads();

    {
        const float4* xg = (const float4*)(x + (size_t)t0 * 64);
        float4* xs4 = (float4*)buf;
        #pragma unroll
        for (int i = tid; i < 2048; i += 256) xs4[i] = xg[i];
    }
    {
        #pragma unroll
        for (int i = tid; i < 3072; i += 256) {
            int ch = i >> 7, xx = i & 127;
            g_kinp[(((size_t)b * 24 + ch) * H + row) * W + xx] = k_s[xx * 25 + ch];
        }
    }
    __syncthreads();

    {
        const int jj = tid >> 5;
        const int cc = tid & 31;
        ull s0 = 0, s1 = 0, s2 = 0;
        const ull* xp = (const ull*)buf;
        #pragma unroll 4
        for (int t = 0; t < 128; t++) {
            ull xv = xp[t * 32 + cc];
            float ka = k_s[t * 25 + jj * 3 + 0];
            float kb = k_s[t * 25 + jj * 3 + 1];
            float kc = k_s[t * 25 + jj * 3 + 2];
            fma2(s0, pack2(ka, ka), xv);
            fma2(s1, pack2(kb, kb), xv);
            fma2(s2, pack2(kc, kc), xv);
        }
        float lo, hi;
        float* Sg = g_SW + b * 1536;
        unpack2(s0, lo, hi);
        atomicAdd(&Sg[(jj * 3 + 0) * 64 + cc * 2], lo);
        atomicAdd(&Sg[(jj * 3 + 0) * 64 + cc * 2 + 1], hi);
        unpack2(s1, lo, hi);
        atomicAdd(&Sg[(jj * 3 + 1) * 64 + cc * 2], lo);
        atomicAdd(&Sg[(jj * 3 + 1) * 64 + cc * 2 + 1], hi);
        unpack2(s2, lo, hi);
        atomicAdd(&Sg[(jj * 3 + 2) * 64 + cc * 2], lo);
        atomicAdd(&Sg[(jj * 3 + 2) * 64 + cc * 2 + 1], hi);
    }
}

// ===========================================================================
// LDG+shfl conv (round 13, measured)
// ===========================================================================
__device__ __forceinline__ void conv_ldg(
    const float* __restrict__ src, const ull* wsp,
    int b, int y, int ocp, int lane, ull acc[4])
{
    const int g = ocp >> 2;
    const int oc0 = ocp * 2;
    #pragma unroll
    for (int r = 0; r < 3; r++) {
        const int gy = y - 1 + r;
        if ((unsigned)gy >= (unsigned)H) continue;
        const float* rowbase = src + (((size_t)b * 24 + g * 8) * H + gy) * W + lane * 4;
        #pragma unroll
        for (int i = 0; i < 8; i++) {
            float4 Bv = __ldg((const float4*)(rowbase + i * NTOK));
            float left = __shfl_up_sync(~0u, Bv.w, 1);
            if (lane == 0) left = 0.f;
            float right = __shfl_down_sync(~0u, Bv.x, 1);
            if (lane == 31) right = 0.f;
            ull P0 = pack2(left, Bv.x);
            ull P1 = pack2(Bv.x, Bv.y);
            ull P2 = pack2(Bv.y, Bv.z);
            ull P3 = pack2(Bv.z, Bv.w);
            ull P4 = pack2(Bv.w, right);
            const int tb = (i * 9 + r * 3) * 24 + oc0;
            {
                ulonglong2 wv = *(const ulonglong2*)&wsp[tb];
                fma2(acc[0], wv.x, P0); fma2(acc[1], wv.x, P2);
                fma2(acc[2], wv.y, P0); fma2(acc[3], wv.y, P2);
            }
            {
                ulonglong2 wv = *(const ulonglong2*)&wsp[tb + 24];
                fma2(acc[0], wv.x, P1); fma2(acc[1], wv.x, P3);
                fma2(acc[2], wv.y, P1); fma2(acc[3], wv.y, P3);
            }
            {
                ulonglong2 wv = *(const ulonglong2*)&wsp[tb + 48];
                fma2(acc[0], wv.x, P2); fma2(acc[1], wv.x, P4);
                fma2(acc[2], wv.y, P2); fma2(acc[3], wv.y, P4);
            }
        }
    }
}

// ===========================================================================
// K4A+K2 merged: grid (129, B), block 384, 4 blocks/SM (42-reg cap).
//  blockIdx.x < 128 : conv1 + GELU -> g_t1, then L2-prefetch of this row's
//                     fea slice (primes k4b's projection reads).
//  blockIdx.x == 128: attention role for heads (2*b, 2*b+1).
// ===========================================================================
__global__ __launch_bounds__(384, 4) void k4a_conv1_k2(
    const float* __restrict__ c1w, const float* __restrict__ fea,
    const float* __restrict__ Wq, const float* __restrict__ Wv,
    const float* __restrict__ Wp, const float* __restrict__ rescale)
{
    __shared__ __align__(16) float smu[6536];
    const int tid = threadIdx.x;

    if (blockIdx.x < 128) {
        // ---- conv role ----
        ull* wsp = (ull*)smu;
        const int b = blockIdx.y;
        const int y = blockIdx.x;

        for (int i = tid; i < 1728; i += 384) {
            int oc = i / 72, r2 = i - oc * 72;
            float w = c1w[i];
            wsp[r2 * 24 + oc] = pack2(w, w);
        }
        __syncthreads();

        const int ocp = tid >> 5, lane = tid & 31;
        ull acc[4] = {0ull, 0ull, 0ull, 0ull};
        conv_ldg(g_kinp, wsp, b, y, ocp, lane, acc);

        float v[8];
        unpack2(acc[0], v[0], v[1]); unpack2(acc[1], v[2], v[3]);
        unpack2(acc[2], v[4], v[5]); unpack2(acc[3], v[6], v[7]);
        #pragma unroll
        for (int q = 0; q < 8; q++) v[q] = gelu_exact(v[q]);
        const int oc0 = ocp * 2;
        float4* d0 = (float4*)(g_t1 + (((size_t)b * 24 + oc0) * H + y) * W + lane * 4);
        float4* d1 = (float4*)(g_t1 + (((size_t)b * 24 + oc0 + 1) * H + y) * W + lane * 4);
        *d0 = make_float4(v[0], v[1], v[2], v[3]);
        *d1 = make_float4(v[4], v[5], v[6], v[7]);

        // L2-prefetch this row's fea slice for k4b (256 x 128B lines)
        if (tid < 256) {
            const char* fp = (const char*)(fea +
                ((size_t)b * NTOK + (size_t)y * W) * 64) + tid * 128;
            asm volatile("prefetch.global.L2 [%0];" :: "l"(fp));
        }
        return;
    }

    // ---- attention role: two heads sequentially ----
    float* wqv_s = smu;            // [64][65]
    float* s_S   = smu + 4160;     // [4][3][64]
    float* s_A   = smu + 4928;     // [4][3][64]
    float* s_M   = smu + 5696;     // [4*64][3]
    float* wp_s  = smu + 6464;     // [3][24]

    for (int hh = 0; hh < 2; hh++) {
        const int h = blockIdx.y * 2 + hh;

        for (int i = tid; i < 4096; i += 384) {
            int c = i >> 6, d = i & 63;
            wqv_s[c * 65 + d] = Wq[c * 512 + h * 64 + d];
        }
        for (int i = tid; i < 768; i += 384) {
            int b2 = i / 192, rem = i - b2 * 192;
            s_S[i] = g_SW[b2 * 1536 + h * 3 * 64 + rem];
        }
        if (tid < 72) {
            int k = tid / 24, o = tid - k * 24;
            wp_s[tid] = Wp[(k * 8 + h) * 24 + o];
        }
        __syncthreads();

        for (int i = tid; i < 768; i += 384) {
            int b2 = i / 192, rem = i - b2 * 192;
            g_SW[b2 * 1536 + h * 3 * 64 + rem] = 0.f;
        }

        const int b = tid >> 6;
        const int d = tid & 63;
        const float sc = rescale[h] * 0.125f;

        if (tid < 256) {
            float a0 = 0.f, a1 = 0.f, a2 = 0.f;
            const float* Sb = s_S + b * 192;
            #pragma unroll 8
            for (int c = 0; c < 64; c++) {
                float wq = wqv_s[c * 65 + d];
                a0 += Sb[c] * wq;
                a1 += Sb[64 + c] * wq;
                a2 += Sb[128 + c] * wq;
            }
            s_A[(b * 3 + 0) * 64 + d] = a0 * sc;
            s_A[(b * 3 + 1) * 64 + d] = a1 * sc;
            s_A[(b * 3 + 2) * 64 + d] = a2 * sc;
        }
        __syncthreads();

        if (tid < 256) {
            const int wid = tid >> 5, lane = tid & 31;
            for (int rowi = wid; rowi < 12; rowi += 8) {
                float v0 = s_A[rowi * 64 + lane];
                float v1 = s_A[rowi * 64 + 32 + lane];
                float m = fmaxf(v0, v1);
                #pragma unroll
                for (int off = 16; off; off >>= 1) m = fmaxf(m, __shfl_xor_sync(~0u, m, off));
                float e0 = __expf(v0 - m), e1 = __expf(v1 - m);
                float s2 = e0 + e1;
                #pragma unroll
                for (int off = 16; off; off >>= 1) s2 += __shfl_xor_sync(~0u, s2, off);
                float inv = 1.0f / s2;
                s_A[rowi * 64 + lane] = e0 * inv;
                s_A[rowi * 64 + 32 + lane] = e1 * inv;
            }
        }
        __syncthreads();

        for (int i = tid; i < 4096; i += 384) {
            int c = i >> 6, dd = i & 63;
            wqv_s[c * 65 + dd] = Wv[c * 512 + h * 64 + dd];
        }
        __syncthreads();

        if (tid < 256) {
            const int c = tid & 63;
            float m0 = 0.f, m1 = 0.f, m2 = 0.f;
            const float* Ab = s_A + b * 192;
            const float* wvr = wqv_s + c * 65;
            #pragma unroll 8
            for (int dd = 0; dd < 64; dd++) {
                float wv = wvr[dd];
                m0 += wv * Ab[dd];
                m1 += wv * Ab[64 + dd];
                m2 += wv * Ab[128 + dd];
            }
            s_M[(b * 64 + c) * 3 + 0] = m0;
            s_M[(b * 64 + c) * 3 + 1] = m1;
            s_M[(b * 64 + c) * 3 + 2] = m2;
        }
        __syncthreads();

        if (tid < 256) {
            const int c = tid & 63;
            const float* mrow = &s_M[(b * 64 + c) * 3];
            float m0 = mrow[0], m1 = mrow[1], m2 = mrow[2];
            float* W2g = g_SW + 6144 + b * 1536 + c * 24;
            #pragma unroll
            for (int o = 0; o < 24; o++) {
                float v = m0 * wp_s[o] + m1 * wp_s[24 + o] + m2 * wp_s[48 + o];
                atomicAdd(&W2g[o], v);
            }
        }
        __syncthreads();
    }
}

// ===========================================================================
// K4B: conv2 (LDG from g_t1, L2-hot) + projection fea@W2+bp + store.
// (round 13 body; now 42-reg cap -> 4 blocks/SM, fea L2-primed by k4a)
// ===========================================================================
__global__ __launch_bounds__(384, 4) void k4b_conv2_proj(
    const float* __restrict__ fea, const float* __restrict__ bp,
    const float* __restrict__ c2w, float* __restrict__ out)
{
    __shared__ __align__(16) ull wsp[1728];
    __shared__ __align__(16) float c2s[24 * 132];
    __shared__ __align__(16) float W2s[1536];
    __shared__ float bps[32];

    const int tid = threadIdx.x;
    const int b = blockIdx.y;
    const int y = blockIdx.x;

    for (int i = tid; i < 1728; i += 384) {
        int oc = i / 72, r2 = i - oc * 72;
        float w = c2w[i];
        wsp[r2 * 24 + oc] = pack2(w, w);
    }
    {
        const float* w2g = g_SW + 6144 + b * 1536;
        for (int i = tid; i < 1536; i += 384) W2s[i] = w2g[i];
    }
    if (tid < 24) bps[tid] = bp[tid];
    __syncthreads();

    const int ocp = tid >> 5, lane = tid & 31;
    ull cacc[4] = {0ull, 0ull, 0ull, 0ull};
    conv_ldg(g_t1, wsp, b, y, ocp, lane, cacc);

    {
        const int oc0 = ocp * 2;
        float cv[8];
        unpack2(cacc[0], cv[0], cv[1]); unpack2(cacc[1], cv[2], cv[3]);
        unpack2(cacc[2], cv[4], cv[5]); unpack2(cacc[3], cv[6], cv[7]);
        *(float4*)(c2s + oc0 * 132 + lane * 4) = make_float4(cv[0], cv[1], cv[2], cv[3]);
        *(float4*)(c2s + (oc0 + 1) * 132 + lane * 4) = make_float4(cv[4], cv[5], cv[6], cv[7]);
    }
    __syncthreads();

    if (tid < 256) {
        const int px = tid >> 1;
        const int ob = (tid & 1) * 12;
        ull acc[6];
        #pragma unroll
        for (int m = 0; m < 6; m++) acc[m] = 0ull;
        const float4* fea4 = (const float4*)(fea +
            ((size_t)b * NTOK + (size_t)y * W + px) * 64);
        #pragma unroll 4
        for (int c4 = 0; c4 < 16; c4++) {
            float4 f = fea4[c4];
            float fe[4] = {f.x, f.y, f.z, f.w};
            #pragma unroll
            for (int e = 0; e < 4; e++) {
                ull f2 = pack2(fe[e], fe[e]);
                const ulonglong2* wrow =
                    (const ulonglong2*)(W2s + (c4 * 4 + e) * 24 + ob);
                ulonglong2 wa = wrow[0];
                fma2(acc[0], wa.x, f2);
                fma2(acc[1], wa.y, f2);
                ulonglong2 wb = wrow[1];
                fma2(acc[2], wb.x, f2);
                fma2(acc[3], wb.y, f2);
                ulonglong2 wc = wrow[2];
                fma2(acc[4], wc.x, f2);
                fma2(acc[5], wc.y, f2);
            }
        }
        float res[12];
        #pragma unroll
        for (int m = 0; m < 6; m++) {
            float lo, hi; unpack2(acc[m], lo, hi);
            res[2 * m] = lo + bps[ob + 2 * m];
            res[2 * m + 1] = hi + bps[ob + 2 * m + 1];
        }
        #pragma unroll
        for (int ch = 0; ch < 12; ch++)
            res[ch] += c2s[(ob + ch) * 132 + px];
        float4* og = (float4*)(out +
            ((size_t)b * NTOK + (size_t)y * W + px) * 24 + ob);
        og[0] = make_float4(res[0], res[1], res[2], res[3]);
        og[1] = make_float4(res[4], res[5], res[6], res[7]);
        og[2] = make_float4(res[8], res[9], res[10], res[11]);
    }
}

// ===========================================================================
extern "C" void kernel_launch(void* const* d_in, const int* in_sizes, int n_in,
                              void* d_out, int out_size)
{
    const float* x = (const float*)d_in[0];
    const float* fea = (const float*)d_in[1];
    const float* im = (const float*)d_in[2];
    const float* Wq = (const float*)d_in[3];
    const float* Wk = (const float*)d_in[4];
    const float* Wv = (const float*)d_in[5];
    const float* rescale = (const float*)d_in[6];
    const float* Wp = (const float*)d_in[7];
    const float* bp = (const float*)d_in[8];
    const float* c1w = (const float*)d_in[9];
    const float* c2w = (const float*)d_in[10];
    float* out = (float*)d_out;

    k1_kinp_S<<<dim3(128, B), 256>>>(x, im, Wk);
    k4a_conv1_k2<<<dim3(129, B), 384>>>(c1w, fea, Wq, Wv, Wp, rescale);
    k4b_conv2_proj<<<dim3(128, B), 384>>>(fea, bp, c2w, out);
}